// round 2
// baseline (speedup 1.0000x reference)
#include <cuda_runtime.h>
#include <math.h>

// Problem constants
#define BB 2
#define TT 2048
#define CC 1024
#define HH 16
#define HD 64
#define MM (BB*TT)        // 4096
#define NQKV (3*CC)       // 3072

// Scratch (device globals — allocation-free)
__device__ float g_q[(size_t)BB*HH*TT*HD];
__device__ float g_k[(size_t)BB*HH*TT*HD];
__device__ float g_v[(size_t)BB*HH*TT*HD];
__device__ float g_y[(size_t)BB*TT*CC];

// ---------------------------------------------------------------------------
// GEMM: out[m,n] = sum_k A[m,k] * W[n,k] + bias[n]
// A: [M,K] row-major, W: [N,K] row-major (torch Linear weight).
// BM=BN=128, BK=16, 256 threads, 8x8 per-thread micro-tile (split 4+4 halves).
// QKV_SCATTER: decode n into (which,head,dim), m into (b,t), write q/k/v scratch
// in [B*H, T, HD] layout. Otherwise write Cout[m*N + n].
// If A == nullptr, read from g_y (proj input).
// ---------------------------------------------------------------------------
template<bool QKV_SCATTER>
__global__ __launch_bounds__(256)
void gemm_nt(const float* __restrict__ A, const float* __restrict__ W,
             const float* __restrict__ bias, float* __restrict__ Cout,
             int K, int N) {
    constexpr int BM = 128, BN = 128, BK = 16;
    __shared__ float As[BK][BM];
    __shared__ float Bs[BK][BN];

    const float* Ap = A ? A : g_y;

    const int tid = threadIdx.x;
    const int tx = tid & 15;       // 0..15 -> output cols
    const int ty = tid >> 4;       // 0..15 -> output rows
    const int m0 = blockIdx.y * BM;
    const int n0 = blockIdx.x * BN;

    float acc[8][8];
#pragma unroll
    for (int i = 0; i < 8; i++)
#pragma unroll
        for (int j = 0; j < 8; j++) acc[i][j] = 0.f;

    // loaders: 128 rows x 16 cols = 512 float4 per tile; 2 per thread
    const int lrow = tid >> 2;          // 0..63
    const int lcol = (tid & 3) * 4;     // 0,4,8,12

    for (int kt = 0; kt < K; kt += BK) {
        __syncthreads();
#pragma unroll
        for (int h = 0; h < 2; h++) {
            int row = lrow + h * 64;
            float4 av = *(const float4*)&Ap[(size_t)(m0 + row) * K + kt + lcol];
            As[lcol + 0][row] = av.x; As[lcol + 1][row] = av.y;
            As[lcol + 2][row] = av.z; As[lcol + 3][row] = av.w;
            float4 bv = *(const float4*)&W[(size_t)(n0 + row) * K + kt + lcol];
            Bs[lcol + 0][row] = bv.x; Bs[lcol + 1][row] = bv.y;
            Bs[lcol + 2][row] = bv.z; Bs[lcol + 3][row] = bv.w;
        }
        __syncthreads();

#pragma unroll
        for (int k = 0; k < BK; k++) {
            float a[8], b[8];
            *(float4*)&a[0] = *(const float4*)&As[k][ty * 4];
            *(float4*)&a[4] = *(const float4*)&As[k][64 + ty * 4];
            *(float4*)&b[0] = *(const float4*)&Bs[k][tx * 4];
            *(float4*)&b[4] = *(const float4*)&Bs[k][64 + tx * 4];
#pragma unroll
            for (int i = 0; i < 8; i++)
#pragma unroll
                for (int j = 0; j < 8; j++)
                    acc[i][j] = fmaf(a[i], b[j], acc[i][j]);
        }
    }

    // epilogue
#pragma unroll
    for (int i = 0; i < 8; i++) {
        int row = m0 + ((i < 4) ? (ty * 4 + i) : (64 + ty * 4 + (i - 4)));
#pragma unroll
        for (int j = 0; j < 8; j++) {
            int col = n0 + ((j < 4) ? (tx * 4 + j) : (64 + tx * 4 + (j - 4)));
            float v = acc[i][j] + bias[col];
            if (QKV_SCATTER) {
                int which = col >> 10;            // /1024 : 0=q,1=k,2=v
                int c = col & (CC - 1);
                int h = c >> 6, d = c & 63;
                int b_ = row >> 11;               // /2048
                int t = row & (TT - 1);
                size_t dst = (((size_t)(b_ * HH + h) * TT + t) * HD) + d;
                float* base = (which == 0) ? g_q : ((which == 1) ? g_k : g_v);
                base[dst] = v;
            } else {
                Cout[(size_t)row * N + col] = v;
            }
        }
    }
}

// ---------------------------------------------------------------------------
// Flash attention, fp32. grid = (T/64, B*H), 256 threads.
// Q tile 64x64 in smem; iterate K/V tiles kj=0..qi (causal block skip).
// Per-thread 4x4 S micro-tile; online softmax with 16-lane shfl reductions
// (stats replicated across tx, which share a 16-lane contiguous group).
// ---------------------------------------------------------------------------
__global__ __launch_bounds__(256)
void attn_kernel() {
    constexpr int LD = 68;                 // smem row stride (16B-aligned rows)
    extern __shared__ float sm[];
    float* Qs = sm;                        // 64*LD
    float* Ks = Qs + 64 * LD;
    float* Vs = Ks + 64 * LD;
    float* Ss = Vs + 64 * LD;

    const int tid = threadIdx.x;
    const int tx = tid & 15;               // cols / dims group
    const int ty = tid >> 4;               // rows group
    const int qi = blockIdx.x;
    const int bh = blockIdx.y;

    const float* Qg = g_q + (size_t)bh * TT * HD + (size_t)qi * 64 * HD;
    const float* Kg = g_k + (size_t)bh * TT * HD;
    const float* Vg = g_v + (size_t)bh * TT * HD;

    for (int e = tid; e < 64 * 64; e += 256) {
        int r = e >> 6, d = e & 63;
        Qs[r * LD + d] = Qg[e];
    }

    float m_s[4], l_s[4], O[4][4];
#pragma unroll
    for (int r = 0; r < 4; r++) {
        m_s[r] = -1e30f; l_s[r] = 0.f;
#pragma unroll
        for (int j = 0; j < 4; j++) O[r][j] = 0.f;
    }

    const float scale = 0.125f;            // 1/sqrt(64)

    for (int kj = 0; kj <= qi; kj++) {
        __syncthreads();                    // protect Ks/Vs/Ss from prev iter
        const float* Kb = Kg + (size_t)kj * 64 * HD;
        const float* Vb = Vg + (size_t)kj * 64 * HD;
        for (int e = tid; e < 64 * 64; e += 256) {
            int r = e >> 6, d = e & 63;
            Ks[r * LD + d] = Kb[e];
            Vs[r * LD + d] = Vb[e];
        }
        __syncthreads();

        // S = Q K^T (4x4 per thread), vectorized over d
        float s[4][4];
#pragma unroll
        for (int r = 0; r < 4; r++)
#pragma unroll
            for (int c = 0; c < 4; c++) s[r][c] = 0.f;

        for (int d = 0; d < 64; d += 4) {
            float4 q4[4], k4[4];
#pragma unroll
            for (int r = 0; r < 4; r++)
                q4[r] = *(const float4*)&Qs[(ty * 4 + r) * LD + d];
#pragma unroll
            for (int c = 0; c < 4; c++)
                k4[c] = *(const float4*)&Ks[(tx * 4 + c) * LD + d];
#pragma unroll
            for (int r = 0; r < 4; r++)
#pragma unroll
                for (int c = 0; c < 4; c++) {
                    s[r][c] = fmaf(q4[r].x, k4[c].x, s[r][c]);
                    s[r][c] = fmaf(q4[r].y, k4[c].y, s[r][c]);
                    s[r][c] = fmaf(q4[r].z, k4[c].z, s[r][c]);
                    s[r][c] = fmaf(q4[r].w, k4[c].w, s[r][c]);
                }
        }

        // scale + causal mask (only diagonal block needs masking)
        const bool diag = (kj == qi);
#pragma unroll
        for (int r = 0; r < 4; r++) {
            int lrow = ty * 4 + r;
#pragma unroll
            for (int c = 0; c < 4; c++) {
                float v = s[r][c] * scale;
                if (diag && (tx * 4 + c) > lrow) v = -1e30f;
                s[r][c] = v;
            }
        }

        // online softmax update (per row, replicated across 16 tx lanes)
#pragma unroll
        for (int r = 0; r < 4; r++) {
            float mx = fmaxf(fmaxf(s[r][0], s[r][1]), fmaxf(s[r][2], s[r][3]));
            mx = fmaxf(mx, __shfl_xor_sync(0xffffffffu, mx, 1));
            mx = fmaxf(mx, __shfl_xor_sync(0xffffffffu, mx, 2));
            mx = fmaxf(mx, __shfl_xor_sync(0xffffffffu, mx, 4));
            mx = fmaxf(mx, __shfl_xor_sync(0xffffffffu, mx, 8));
            float m_new = fmaxf(m_s[r], mx);
            float corr = __expf(m_s[r] - m_new);
            m_s[r] = m_new;
            float rs = 0.f;
#pragma unroll
            for (int c = 0; c < 4; c++) {
                float p = __expf(s[r][c] - m_new);
                s[r][c] = p;
                rs += p;
            }
            rs += __shfl_xor_sync(0xffffffffu, rs, 1);
            rs += __shfl_xor_sync(0xffffffffu, rs, 2);
            rs += __shfl_xor_sync(0xffffffffu, rs, 4);
            rs += __shfl_xor_sync(0xffffffffu, rs, 8);
            l_s[r] = l_s[r] * corr + rs;
#pragma unroll
            for (int j = 0; j < 4; j++) O[r][j] *= corr;
        }

        // store P to smem for the PV gemm
#pragma unroll
        for (int r = 0; r < 4; r++) {
            float4 pv = make_float4(s[r][0], s[r][1], s[r][2], s[r][3]);
            *(float4*)&Ss[(ty * 4 + r) * LD + tx * 4] = pv;
        }
        __syncthreads();

        // O += P @ V  (rows ty*4.., dims tx*4..)
        for (int c = 0; c < 64; c++) {
            float4 v4 = *(const float4*)&Vs[c * LD + tx * 4];
            float p0 = Ss[(ty * 4 + 0) * LD + c];
            float p1 = Ss[(ty * 4 + 1) * LD + c];
            float p2 = Ss[(ty * 4 + 2) * LD + c];
            float p3 = Ss[(ty * 4 + 3) * LD + c];
            O[0][0] = fmaf(p0, v4.x, O[0][0]); O[0][1] = fmaf(p0, v4.y, O[0][1]);
            O[0][2] = fmaf(p0, v4.z, O[0][2]); O[0][3] = fmaf(p0, v4.w, O[0][3]);
            O[1][0] = fmaf(p1, v4.x, O[1][0]); O[1][1] = fmaf(p1, v4.y, O[1][1]);
            O[1][2] = fmaf(p1, v4.z, O[1][2]); O[1][3] = fmaf(p1, v4.w, O[1][3]);
            O[2][0] = fmaf(p2, v4.x, O[2][0]); O[2][1] = fmaf(p2, v4.y, O[2][1]);
            O[2][2] = fmaf(p2, v4.z, O[2][2]); O[2][3] = fmaf(p2, v4.w, O[2][3]);
            O[3][0] = fmaf(p3, v4.x, O[3][0]); O[3][1] = fmaf(p3, v4.y, O[3][1]);
            O[3][2] = fmaf(p3, v4.z, O[3][2]); O[3][3] = fmaf(p3, v4.w, O[3][3]);
        }
    }

    // write y in [B,T,C] layout for the proj GEMM
    const int b_ = bh / HH, h = bh % HH;
#pragma unroll
    for (int r = 0; r < 4; r++) {
        float inv = 1.f / l_s[r];
        int t = qi * 64 + ty * 4 + r;
        float4 o4 = make_float4(O[r][0] * inv, O[r][1] * inv,
                                O[r][2] * inv, O[r][3] * inv);
        *(float4*)&g_y[((size_t)b_ * TT + t) * CC + h * HD + tx * 4] = o4;
    }
}

// ---------------------------------------------------------------------------
// Launch: qkv GEMM -> flash attention -> proj GEMM
// Inputs (metadata order): x, W_attn, b_attn, W_proj, b_proj. Output fp32 [B,T,C].
// ---------------------------------------------------------------------------
static const int kAttnSmemBytes = 4 * 64 * 68 * (int)sizeof(float);  // 69632

extern "C" void kernel_launch(void* const* d_in, const int* in_sizes, int n_in,
                              void* d_out, int out_size) {
    const float* x      = (const float*)d_in[0];
    const float* W_attn = (const float*)d_in[1];
    const float* b_attn = (const float*)d_in[2];
    const float* W_proj = (const float*)d_in[3];
    const float* b_proj = (const float*)d_in[4];
    float* out = (float*)d_out;

    // 1) qkv = x @ W_attn^T + b_attn, scattered into per-head q/k/v scratch
    gemm_nt<true><<<dim3(NQKV / 128, MM / 128), 256>>>(
        x, W_attn, b_attn, nullptr, CC, NQKV);

    // 2) flash attention (>48KB smem needs the opt-in; not a stream op, capture-safe)
    cudaFuncSetAttribute(attn_kernel,
                         cudaFuncAttributeMaxDynamicSharedMemorySize,
                         kAttnSmemBytes);
    attn_kernel<<<dim3(TT / 64, BB * HH), 256, kAttnSmemBytes>>>();

    // 3) out = y @ W_proj^T + b_proj
    gemm_nt<false><<<dim3(CC / 128, MM / 128), 256>>>(
        nullptr, W_proj, b_proj, out, CC, CC);
}

// round 3
// speedup vs baseline: 1.5671x; 1.5671x over previous
#include <cuda_runtime.h>
#include <math.h>

// Problem constants
#define BB 2
#define TT 2048
#define CC 1024
#define HH 16
#define HD 64
#define MM (BB*TT)        // 4096
#define NQKV (3*CC)       // 3072

// Scratch (device globals — allocation-free)
__device__ float g_q[(size_t)BB*HH*TT*HD];
__device__ float g_k[(size_t)BB*HH*TT*HD];
__device__ float g_v[(size_t)BB*HH*TT*HD];
__device__ float g_y[(size_t)BB*TT*CC];

// ---------------------------------------------------------------------------
// Helpers: tf32 conversion + m16n8k8 tf32 mma (legacy HMMA path on sm_100a)
// ---------------------------------------------------------------------------
__device__ __forceinline__ unsigned f2tf(float x) {
    unsigned r;
    asm("cvt.rna.tf32.f32 %0, %1;" : "=r"(r) : "f"(x));
    return r;
}
__device__ __forceinline__ float uaf(unsigned x) { return __uint_as_float(x); }
__device__ __forceinline__ unsigned fau(float x) { return __float_as_uint(x); }

__device__ __forceinline__ void mma_tf32(float d[4], const unsigned a[4],
                                         unsigned b0, unsigned b1) {
    asm volatile(
        "mma.sync.aligned.m16n8k8.row.col.f32.tf32.tf32.f32 "
        "{%0,%1,%2,%3}, {%4,%5,%6,%7}, {%8,%9}, {%0,%1,%2,%3};"
        : "+f"(d[0]), "+f"(d[1]), "+f"(d[2]), "+f"(d[3])
        : "r"(a[0]), "r"(a[1]), "r"(a[2]), "r"(a[3]), "r"(b0), "r"(b1));
}

// ---------------------------------------------------------------------------
// Tensor-core GEMM (3xTF32): out[m,n] = sum_k A[m,k]*W[n,k] + bias[n]
// 128x128x32 tile, 256 threads = 8 warps in 2x4, warp tile 64x32.
// smem pad LDK=36 -> fragment LDS bank == lane (conflict-free).
// QKV_SCATTER: scatter epilogue into g_q/g_k/g_v per-head layout.
// A == nullptr means read from g_y.
// ---------------------------------------------------------------------------
template<bool QKV_SCATTER>
__global__ __launch_bounds__(256, 1)
void gemm_tc(const float* __restrict__ A, const float* __restrict__ W,
             const float* __restrict__ bias, float* __restrict__ Cout,
             int K, int N) {
    constexpr int BM = 128, BN = 128, BK = 32, LDK = 36;
    __shared__ float As[BM * LDK];
    __shared__ float Ws[BN * LDK];

    const float* Ap = A ? A : g_y;

    const int tid = threadIdx.x;
    const int lane = tid & 31, w = tid >> 5;
    const int g = lane >> 2, t = lane & 3;
    const int m0 = blockIdx.y * BM, n0 = blockIdx.x * BN;
    const int wm = (w >> 2) * 64;    // warp row offset (0 or 64)
    const int wn = (w & 3) * 32;     // warp col offset (0,32,64,96)

    float acc[4][4][4] = {};         // [mi][ni][frag]

    for (int kt = 0; kt < K; kt += BK) {
        __syncthreads();
        // load 128x32 A and W tiles (4 float4 per thread each)
#pragma unroll
        for (int i = 0; i < 4; i++) {
            int c = tid + 256 * i;           // 0..1023
            int row = c >> 3, col = (c & 7) * 4;
            *(float4*)&As[row * LDK + col] =
                *(const float4*)&Ap[(size_t)(m0 + row) * K + kt + col];
            *(float4*)&Ws[row * LDK + col] =
                *(const float4*)&W[(size_t)(n0 + row) * K + kt + col];
        }
        __syncthreads();

#pragma unroll
        for (int s = 0; s < 4; s++) {        // k-slices of 8
            const int k0 = s * 8;
            unsigned ah[4][4], al[4][4];
#pragma unroll
            for (int mi = 0; mi < 4; mi++) {
                const int r = wm + mi * 16;
                float x0 = As[(r + g) * LDK + k0 + t];
                float x1 = As[(r + g + 8) * LDK + k0 + t];
                float x2 = As[(r + g) * LDK + k0 + t + 4];
                float x3 = As[(r + g + 8) * LDK + k0 + t + 4];
                ah[mi][0] = f2tf(x0); al[mi][0] = f2tf(x0 - uaf(ah[mi][0]));
                ah[mi][1] = f2tf(x1); al[mi][1] = f2tf(x1 - uaf(ah[mi][1]));
                ah[mi][2] = f2tf(x2); al[mi][2] = f2tf(x2 - uaf(ah[mi][2]));
                ah[mi][3] = f2tf(x3); al[mi][3] = f2tf(x3 - uaf(ah[mi][3]));
            }
            unsigned bh0[4], bh1[4], bl0[4], bl1[4];
#pragma unroll
            for (int ni = 0; ni < 4; ni++) {
                const int c0 = wn + ni * 8;
                float y0 = Ws[(c0 + g) * LDK + k0 + t];
                float y1 = Ws[(c0 + g) * LDK + k0 + t + 4];
                bh0[ni] = f2tf(y0); bl0[ni] = f2tf(y0 - uaf(bh0[ni]));
                bh1[ni] = f2tf(y1); bl1[ni] = f2tf(y1 - uaf(bh1[ni]));
            }
#pragma unroll
            for (int mi = 0; mi < 4; mi++)
#pragma unroll
                for (int ni = 0; ni < 4; ni++) {
                    mma_tf32(acc[mi][ni], ah[mi], bh0[ni], bh1[ni]);
                    mma_tf32(acc[mi][ni], al[mi], bh0[ni], bh1[ni]);
                    mma_tf32(acc[mi][ni], ah[mi], bl0[ni], bl1[ni]);
                }
        }
    }

    // epilogue
#pragma unroll
    for (int mi = 0; mi < 4; mi++)
#pragma unroll
        for (int ni = 0; ni < 4; ni++)
#pragma unroll
            for (int e = 0; e < 4; e++) {
                int row = m0 + wm + mi * 16 + g + ((e >= 2) ? 8 : 0);
                int col = n0 + wn + ni * 8 + 2 * t + (e & 1);
                float v = acc[mi][ni][e] + __ldg(&bias[col]);
                if (QKV_SCATTER) {
                    int which = col >> 10;          // 0=q,1=k,2=v
                    int c = col & (CC - 1);
                    int h = c >> 6, d = c & 63;
                    int b_ = row >> 11;
                    int tt = row & (TT - 1);
                    size_t dst = (((size_t)(b_ * HH + h) * TT + tt) * HD) + d;
                    float* base = (which == 0) ? g_q : ((which == 1) ? g_k : g_v);
                    base[dst] = v;
                } else {
                    Cout[(size_t)row * N + col] = v;
                }
            }
}

// ---------------------------------------------------------------------------
// Tensor-core flash attention (3xTF32).
// grid = (T/128, B*H), 256 threads = 8 warps; warp w owns q-rows [16w,16w+16).
// K/V 64-key tiles staged in smem pre-split hi/lo (pads 68/72 = conflict-free
// B-frag loads). Online softmax on C-frags; P via per-warp smem round-trip.
// Q pre-scaled by 1/8 and kept as hi/lo A-frags in registers.
// ---------------------------------------------------------------------------
__global__ __launch_bounds__(256, 1)
void attn_tc() {
    extern __shared__ float smf[];
    float* Khs = smf;                  // [64][68] hi
    float* Kls = Khs + 64 * 68;        // [64][68] lo
    float* Vhs = Kls + 64 * 68;        // [64][72] hi
    float* Vls = Vhs + 64 * 72;        // [64][72] lo
    float* Ps  = Vls + 64 * 72;        // [128][68] probabilities

    const int tid = threadIdx.x;
    const int lane = tid & 31, w = tid >> 5;
    const int g = lane >> 2, t = lane & 3;
    const int qi = (int)gridDim.x - 1 - (int)blockIdx.x;  // big tiles first
    const int bh_ = blockIdx.y;

    const float* Qg = g_q + (size_t)bh_ * TT * HD;
    const float* Kg = g_k + (size_t)bh_ * TT * HD;
    const float* Vg = g_v + (size_t)bh_ * TT * HD;

    const int qrow0 = qi * 128 + w * 16;

    // Q fragments (scaled by 1/sqrt(64)=0.125, exact), hi/lo, in registers
    unsigned qh[8][4], ql[8][4];
#pragma unroll
    for (int s = 0; s < 8; s++) {
        float x0 = Qg[(size_t)(qrow0 + g) * 64 + s * 8 + t] * 0.125f;
        float x1 = Qg[(size_t)(qrow0 + g + 8) * 64 + s * 8 + t] * 0.125f;
        float x2 = Qg[(size_t)(qrow0 + g) * 64 + s * 8 + t + 4] * 0.125f;
        float x3 = Qg[(size_t)(qrow0 + g + 8) * 64 + s * 8 + t + 4] * 0.125f;
        qh[s][0] = f2tf(x0); ql[s][0] = f2tf(x0 - uaf(qh[s][0]));
        qh[s][1] = f2tf(x1); ql[s][1] = f2tf(x1 - uaf(qh[s][1]));
        qh[s][2] = f2tf(x2); ql[s][2] = f2tf(x2 - uaf(qh[s][2]));
        qh[s][3] = f2tf(x3); ql[s][3] = f2tf(x3 - uaf(qh[s][3]));
    }

    float m0s = -1e30f, m1s = -1e30f, l0s = 0.f, l1s = 0.f;
    float O[8][4] = {};

    const int nkb = 2 * qi + 2;
    for (int kb = 0; kb < nkb; kb++) {
        const int k0 = kb * 64;
        __syncthreads();                    // protect smem from prev readers
        // cooperative K/V tile load + hi/lo split
#pragma unroll
        for (int i = 0; i < 4; i++) {
            int c = tid + 256 * i;          // 1024 float4 chunks
            int key = c >> 4, hd4 = (c & 15) * 4;
            float4 kv = *(const float4*)&Kg[(size_t)(k0 + key) * 64 + hd4];
            float4 kh, kl;
            kh.x = uaf(f2tf(kv.x)); kl.x = kv.x - kh.x;
            kh.y = uaf(f2tf(kv.y)); kl.y = kv.y - kh.y;
            kh.z = uaf(f2tf(kv.z)); kl.z = kv.z - kh.z;
            kh.w = uaf(f2tf(kv.w)); kl.w = kv.w - kh.w;
            *(float4*)&Khs[key * 68 + hd4] = kh;
            *(float4*)&Kls[key * 68 + hd4] = kl;
            float4 vv = *(const float4*)&Vg[(size_t)(k0 + key) * 64 + hd4];
            float4 vh, vl;
            vh.x = uaf(f2tf(vv.x)); vl.x = vv.x - vh.x;
            vh.y = uaf(f2tf(vv.y)); vl.y = vv.y - vh.y;
            vh.z = uaf(f2tf(vv.z)); vl.z = vv.z - vh.z;
            vh.w = uaf(f2tf(vv.w)); vl.w = vv.w - vh.w;
            *(float4*)&Vhs[key * 72 + hd4] = vh;
            *(float4*)&Vls[key * 72 + hd4] = vl;
        }
        __syncthreads();

        if (k0 <= qrow0 + 15) {             // warp has unmasked keys here
            // ---- S = Q K^T (pre-scaled) ----
            float S[8][4] = {};
#pragma unroll
            for (int n = 0; n < 8; n++) {
#pragma unroll
                for (int s = 0; s < 8; s++) {
                    float kh0 = Khs[(n * 8 + g) * 68 + s * 8 + t];
                    float kh1 = Khs[(n * 8 + g) * 68 + s * 8 + t + 4];
                    float kl0f = Kls[(n * 8 + g) * 68 + s * 8 + t];
                    float kl1f = Kls[(n * 8 + g) * 68 + s * 8 + t + 4];
                    unsigned b0h = fau(kh0), b1h = fau(kh1);
                    unsigned b0l = f2tf(kl0f), b1l = f2tf(kl1f);
                    mma_tf32(S[n], qh[s], b0h, b1h);
                    mma_tf32(S[n], ql[s], b0h, b1h);
                    mma_tf32(S[n], qh[s], b0l, b1l);
                }
            }
            // ---- causal mask (only near diagonal) ----
            if (k0 + 63 > qrow0) {
                int r0 = qrow0 + g, r1 = r0 + 8;
#pragma unroll
                for (int n = 0; n < 8; n++) {
                    int cb = k0 + n * 8 + 2 * t;
                    if (cb > r0)     S[n][0] = -1e30f;
                    if (cb + 1 > r0) S[n][1] = -1e30f;
                    if (cb > r1)     S[n][2] = -1e30f;
                    if (cb + 1 > r1) S[n][3] = -1e30f;
                }
            }
            // ---- online softmax (rows g and g+8; quad reduce over t) ----
            float mx0 = -1e30f, mx1 = -1e30f;
#pragma unroll
            for (int n = 0; n < 8; n++) {
                mx0 = fmaxf(mx0, fmaxf(S[n][0], S[n][1]));
                mx1 = fmaxf(mx1, fmaxf(S[n][2], S[n][3]));
            }
            mx0 = fmaxf(mx0, __shfl_xor_sync(0xffffffffu, mx0, 1));
            mx0 = fmaxf(mx0, __shfl_xor_sync(0xffffffffu, mx0, 2));
            mx1 = fmaxf(mx1, __shfl_xor_sync(0xffffffffu, mx1, 1));
            mx1 = fmaxf(mx1, __shfl_xor_sync(0xffffffffu, mx1, 2));
            float mn0 = fmaxf(m0s, mx0), mn1 = fmaxf(m1s, mx1);
            float cr0 = __expf(m0s - mn0), cr1 = __expf(m1s - mn1);
            m0s = mn0; m1s = mn1;
            float rs0 = 0.f, rs1 = 0.f;
#pragma unroll
            for (int n = 0; n < 8; n++) {
                S[n][0] = __expf(S[n][0] - mn0);
                S[n][1] = __expf(S[n][1] - mn0);
                S[n][2] = __expf(S[n][2] - mn1);
                S[n][3] = __expf(S[n][3] - mn1);
                rs0 += S[n][0] + S[n][1];
                rs1 += S[n][2] + S[n][3];
            }
            rs0 += __shfl_xor_sync(0xffffffffu, rs0, 1);
            rs0 += __shfl_xor_sync(0xffffffffu, rs0, 2);
            rs1 += __shfl_xor_sync(0xffffffffu, rs1, 1);
            rs1 += __shfl_xor_sync(0xffffffffu, rs1, 2);
            l0s = l0s * cr0 + rs0;
            l1s = l1s * cr1 + rs1;
#pragma unroll
            for (int n = 0; n < 8; n++) {
                O[n][0] *= cr0; O[n][1] *= cr0;
                O[n][2] *= cr1; O[n][3] *= cr1;
            }
            // ---- P -> per-warp smem slab ----
#pragma unroll
            for (int n = 0; n < 8; n++) {
                *(float2*)&Ps[(w * 16 + g) * 68 + n * 8 + 2 * t] =
                    make_float2(S[n][0], S[n][1]);
                *(float2*)&Ps[(w * 16 + g + 8) * 68 + n * 8 + 2 * t] =
                    make_float2(S[n][2], S[n][3]);
            }
            __syncwarp();
            // ---- O += P V ----
#pragma unroll
            for (int s = 0; s < 8; s++) {
                float p0 = Ps[(w * 16 + g) * 68 + s * 8 + t];
                float p1 = Ps[(w * 16 + g + 8) * 68 + s * 8 + t];
                float p2 = Ps[(w * 16 + g) * 68 + s * 8 + t + 4];
                float p3 = Ps[(w * 16 + g + 8) * 68 + s * 8 + t + 4];
                unsigned pah[4], pal[4];
                pah[0] = f2tf(p0); pal[0] = f2tf(p0 - uaf(pah[0]));
                pah[1] = f2tf(p1); pal[1] = f2tf(p1 - uaf(pah[1]));
                pah[2] = f2tf(p2); pal[2] = f2tf(p2 - uaf(pah[2]));
                pah[3] = f2tf(p3); pal[3] = f2tf(p3 - uaf(pah[3]));
#pragma unroll
                for (int n = 0; n < 8; n++) {
                    float vh0 = Vhs[(s * 8 + t) * 72 + n * 8 + g];
                    float vh1 = Vhs[(s * 8 + t + 4) * 72 + n * 8 + g];
                    float vl0f = Vls[(s * 8 + t) * 72 + n * 8 + g];
                    float vl1f = Vls[(s * 8 + t + 4) * 72 + n * 8 + g];
                    unsigned b0h = fau(vh0), b1h = fau(vh1);
                    unsigned b0l = f2tf(vl0f), b1l = f2tf(vl1f);
                    mma_tf32(O[n], pah, b0h, b1h);
                    mma_tf32(O[n], pal, b0h, b1h);
                    mma_tf32(O[n], pah, b0l, b1l);
                }
            }
        }
    }

    // epilogue: y[B,T,C] for the proj GEMM
    const int b_ = bh_ / HH, h = bh_ % HH;
    const float inv0 = 1.f / l0s, inv1 = 1.f / l1s;
#pragma unroll
    for (int n = 0; n < 8; n++) {
        int col = h * 64 + n * 8 + 2 * t;
        int r0 = qrow0 + g;
        *(float2*)&g_y[((size_t)b_ * TT + r0) * CC + col] =
            make_float2(O[n][0] * inv0, O[n][1] * inv0);
        *(float2*)&g_y[((size_t)b_ * TT + r0 + 8) * CC + col] =
            make_float2(O[n][2] * inv1, O[n][3] * inv1);
    }
}

// ---------------------------------------------------------------------------
// Launch: qkv GEMM -> flash attention -> proj GEMM
// Inputs: x, W_attn, b_attn, W_proj, b_proj. Output fp32 [B,T,C].
// ---------------------------------------------------------------------------
static const int kAttnSmem = (2 * 64 * 68 + 2 * 64 * 72 + 128 * 68) * (int)sizeof(float);

extern "C" void kernel_launch(void* const* d_in, const int* in_sizes, int n_in,
                              void* d_out, int out_size) {
    const float* x      = (const float*)d_in[0];
    const float* W_attn = (const float*)d_in[1];
    const float* b_attn = (const float*)d_in[2];
    const float* W_proj = (const float*)d_in[3];
    const float* b_proj = (const float*)d_in[4];
    float* out = (float*)d_out;

    // 1) qkv projection (tensor core, scatter into per-head q/k/v)
    gemm_tc<true><<<dim3(NQKV / 128, MM / 128), 256>>>(
        x, W_attn, b_attn, nullptr, CC, NQKV);

    // 2) flash attention (tensor core), ~104KB dynamic smem
    cudaFuncSetAttribute(attn_tc,
                         cudaFuncAttributeMaxDynamicSharedMemorySize, kAttnSmem);
    attn_tc<<<dim3(TT / 128, BB * HH), 256, kAttnSmem>>>();

    // 3) output projection (tensor core)
    gemm_tc<false><<<dim3(CC / 128, MM / 128), 256>>>(
        nullptr, W_proj, b_proj, out, CC, CC);
}

// round 4
// speedup vs baseline: 1.7960x; 1.1461x over previous
#include <cuda_runtime.h>
#include <math.h>

// Problem constants
#define BB 2
#define TT 2048
#define CC 1024
#define HH 16
#define HD 64
#define MM (BB*TT)        // 4096
#define NQKV (3*CC)       // 3072

// Scratch (device globals — allocation-free)
__device__ float g_q[(size_t)BB*HH*TT*HD];
__device__ float g_k[(size_t)BB*HH*TT*HD];
__device__ float g_v[(size_t)BB*HH*TT*HD];
__device__ float g_y[(size_t)BB*TT*CC];

// ---------------------------------------------------------------------------
// Helpers: tf32 conversion + m16n8k8 tf32 mma
// tf32 register format == fp32 bits with low mantissa zeroed, so values stored
// pre-rounded in smem can be fed to mma via plain reinterpret (fau).
// ---------------------------------------------------------------------------
__device__ __forceinline__ unsigned f2tf(float x) {
    unsigned r;
    asm("cvt.rna.tf32.f32 %0, %1;" : "=r"(r) : "f"(x));
    return r;
}
__device__ __forceinline__ float uaf(unsigned x) { return __uint_as_float(x); }
__device__ __forceinline__ unsigned fau(float x) { return __float_as_uint(x); }

__device__ __forceinline__ void mma_tf32(float d[4], const unsigned a[4],
                                         unsigned b0, unsigned b1) {
    asm volatile(
        "mma.sync.aligned.m16n8k8.row.col.f32.tf32.tf32.f32 "
        "{%0,%1,%2,%3}, {%4,%5,%6,%7}, {%8,%9}, {%0,%1,%2,%3};"
        : "+f"(d[0]), "+f"(d[1]), "+f"(d[2]), "+f"(d[3])
        : "r"(a[0]), "r"(a[1]), "r"(a[2]), "r"(a[3]), "r"(b0), "r"(b1));
}

// split x into tf32-rounded hi/lo (both stored as fp32 bit patterns)
__device__ __forceinline__ void split4(float4 v, float4& h, float4& l) {
    h.x = uaf(f2tf(v.x)); l.x = uaf(f2tf(v.x - h.x));
    h.y = uaf(f2tf(v.y)); l.y = uaf(f2tf(v.y - h.y));
    h.z = uaf(f2tf(v.z)); l.z = uaf(f2tf(v.z - h.z));
    h.w = uaf(f2tf(v.w)); l.w = uaf(f2tf(v.w - h.w));
}

// ---------------------------------------------------------------------------
// Tensor-core GEMM (3xTF32): out[m,n] = sum_k A[m,k]*W[n,k] + bias[n]
// 128x128x32 tile, 256 threads = 8 warps (2x4), warp tile 64x32.
// Hi/lo pre-split into smem once per element; inner loop = LDS + MMA only.
// Register double-buffer: LDG next tile while computing current.
// ---------------------------------------------------------------------------
template<bool QKV_SCATTER>
__global__ __launch_bounds__(256, 1)
void gemm_tc(const float* __restrict__ A, const float* __restrict__ W,
             const float* __restrict__ bias, float* __restrict__ Cout,
             int K, int N) {
    constexpr int BM = 128, BK = 32, LDK = 36;
    extern __shared__ float sm[];
    float* Ah = sm;                    // [BM][LDK]
    float* Al = Ah + BM * LDK;
    float* Wh = Al + BM * LDK;
    float* Wl = Wh + BM * LDK;

    const float* Ap = A ? A : g_y;

    const int tid = threadIdx.x;
    const int lane = tid & 31, w = tid >> 5;
    const int g = lane >> 2, t = lane & 3;
    const int m0 = blockIdx.y * BM, n0 = blockIdx.x * BM;
    const int wm = (w >> 2) * 64;
    const int wn = (w & 3) * 32;

    // loader indices: 4 float4 per matrix per tile
    const int lrow = tid >> 3;              // 0..31 (+32*i)
    const int lcol = (tid & 7) * 4;         // 0..28

    float acc[4][4][4] = {};

    // prologue: load tile 0 into registers
    float4 ra[4], rw[4];
#pragma unroll
    for (int i = 0; i < 4; i++) {
        int row = lrow + 32 * i;
        ra[i] = *(const float4*)&Ap[(size_t)(m0 + row) * K + lcol];
        rw[i] = *(const float4*)&W[(size_t)(n0 + row) * K + lcol];
    }

    for (int kt = 0; kt < K; kt += BK) {
        __syncthreads();                    // prior compute done with hi/lo
        // convert + store current tile
#pragma unroll
        for (int i = 0; i < 4; i++) {
            int row = lrow + 32 * i;
            float4 h, l;
            split4(ra[i], h, l);
            *(float4*)&Ah[row * LDK + lcol] = h;
            *(float4*)&Al[row * LDK + lcol] = l;
            split4(rw[i], h, l);
            *(float4*)&Wh[row * LDK + lcol] = h;
            *(float4*)&Wl[row * LDK + lcol] = l;
        }
        // prefetch next tile into registers (overlaps with compute below)
        if (kt + BK < K) {
#pragma unroll
            for (int i = 0; i < 4; i++) {
                int row = lrow + 32 * i;
                ra[i] = *(const float4*)&Ap[(size_t)(m0 + row) * K + kt + BK + lcol];
                rw[i] = *(const float4*)&W[(size_t)(n0 + row) * K + kt + BK + lcol];
            }
        }
        __syncthreads();

#pragma unroll
        for (int s = 0; s < 4; s++) {       // k-slices of 8
            const int k0 = s * 8;
            unsigned ah[4][4], al[4][4];
#pragma unroll
            for (int mi = 0; mi < 4; mi++) {
                const int r = wm + mi * 16;
                ah[mi][0] = fau(Ah[(r + g) * LDK + k0 + t]);
                ah[mi][1] = fau(Ah[(r + g + 8) * LDK + k0 + t]);
                ah[mi][2] = fau(Ah[(r + g) * LDK + k0 + t + 4]);
                ah[mi][3] = fau(Ah[(r + g + 8) * LDK + k0 + t + 4]);
                al[mi][0] = fau(Al[(r + g) * LDK + k0 + t]);
                al[mi][1] = fau(Al[(r + g + 8) * LDK + k0 + t]);
                al[mi][2] = fau(Al[(r + g) * LDK + k0 + t + 4]);
                al[mi][3] = fau(Al[(r + g + 8) * LDK + k0 + t + 4]);
            }
            unsigned bh0[4], bh1[4], bl0[4], bl1[4];
#pragma unroll
            for (int ni = 0; ni < 4; ni++) {
                const int c0 = wn + ni * 8;
                bh0[ni] = fau(Wh[(c0 + g) * LDK + k0 + t]);
                bh1[ni] = fau(Wh[(c0 + g) * LDK + k0 + t + 4]);
                bl0[ni] = fau(Wl[(c0 + g) * LDK + k0 + t]);
                bl1[ni] = fau(Wl[(c0 + g) * LDK + k0 + t + 4]);
            }
#pragma unroll
            for (int mi = 0; mi < 4; mi++)
#pragma unroll
                for (int ni = 0; ni < 4; ni++) {
                    mma_tf32(acc[mi][ni], ah[mi], bh0[ni], bh1[ni]);
                    mma_tf32(acc[mi][ni], al[mi], bh0[ni], bh1[ni]);
                    mma_tf32(acc[mi][ni], ah[mi], bl0[ni], bl1[ni]);
                }
        }
    }

    // epilogue
#pragma unroll
    for (int mi = 0; mi < 4; mi++)
#pragma unroll
        for (int ni = 0; ni < 4; ni++)
#pragma unroll
            for (int e = 0; e < 4; e++) {
                int row = m0 + wm + mi * 16 + g + ((e >= 2) ? 8 : 0);
                int col = n0 + wn + ni * 8 + 2 * t + (e & 1);
                float v = acc[mi][ni][e] + __ldg(&bias[col]);
                if (QKV_SCATTER) {
                    int which = col >> 10;          // 0=q,1=k,2=v
                    int c = col & (CC - 1);
                    int h = c >> 6, d = c & 63;
                    int b_ = row >> 11;
                    int tt = row & (TT - 1);
                    size_t dst = (((size_t)(b_ * HH + h) * TT + tt) * HD) + d;
                    float* base = (which == 0) ? g_q : ((which == 1) ? g_k : g_v);
                    base[dst] = v;
                } else {
                    Cout[(size_t)row * N + col] = v;
                }
            }
}

// ---------------------------------------------------------------------------
// Tensor-core flash attention (3xTF32).
// grid = (T/128, B*H), 256 threads = 8 warps; warp w owns q-rows [16w,16w+16).
// K/V tiles hi/lo pre-split (tf32-rounded) in smem; P hi/lo pre-split at the
// smem store. Inner loops are pure LDS + MMA.
// ---------------------------------------------------------------------------
__global__ __launch_bounds__(256, 1)
void attn_tc() {
    extern __shared__ float smf[];
    float* Khs = smf;                  // [64][68]
    float* Kls = Khs + 64 * 68;
    float* Vhs = Kls + 64 * 68;        // [64][72]
    float* Vls = Vhs + 64 * 72;
    float* Phs = Vls + 64 * 72;        // [128][68]
    float* Pls = Phs + 128 * 68;

    const int tid = threadIdx.x;
    const int lane = tid & 31, w = tid >> 5;
    const int g = lane >> 2, t = lane & 3;
    const int qi = (int)gridDim.x - 1 - (int)blockIdx.x;  // big tiles first
    const int bh_ = blockIdx.y;

    const float* Qg = g_q + (size_t)bh_ * TT * HD;
    const float* Kg = g_k + (size_t)bh_ * TT * HD;
    const float* Vg = g_v + (size_t)bh_ * TT * HD;

    const int qrow0 = qi * 128 + w * 16;

    // Q fragments (scaled by 1/8, exact), hi/lo, registers
    unsigned qh[8][4], ql[8][4];
#pragma unroll
    for (int s = 0; s < 8; s++) {
        float x0 = Qg[(size_t)(qrow0 + g) * 64 + s * 8 + t] * 0.125f;
        float x1 = Qg[(size_t)(qrow0 + g + 8) * 64 + s * 8 + t] * 0.125f;
        float x2 = Qg[(size_t)(qrow0 + g) * 64 + s * 8 + t + 4] * 0.125f;
        float x3 = Qg[(size_t)(qrow0 + g + 8) * 64 + s * 8 + t + 4] * 0.125f;
        qh[s][0] = f2tf(x0); ql[s][0] = f2tf(x0 - uaf(qh[s][0]));
        qh[s][1] = f2tf(x1); ql[s][1] = f2tf(x1 - uaf(qh[s][1]));
        qh[s][2] = f2tf(x2); ql[s][2] = f2tf(x2 - uaf(qh[s][2]));
        qh[s][3] = f2tf(x3); ql[s][3] = f2tf(x3 - uaf(qh[s][3]));
    }

    float m0s = -1e30f, m1s = -1e30f, l0s = 0.f, l1s = 0.f;
    float O[8][4] = {};

    const int nkb = 2 * qi + 2;
    for (int kb = 0; kb < nkb; kb++) {
        const int k0 = kb * 64;
        __syncthreads();
        // cooperative K/V tile load + tf32 hi/lo split
#pragma unroll
        for (int i = 0; i < 4; i++) {
            int c = tid + 256 * i;
            int key = c >> 4, hd4 = (c & 15) * 4;
            float4 h, l;
            split4(*(const float4*)&Kg[(size_t)(k0 + key) * 64 + hd4], h, l);
            *(float4*)&Khs[key * 68 + hd4] = h;
            *(float4*)&Kls[key * 68 + hd4] = l;
            split4(*(const float4*)&Vg[(size_t)(k0 + key) * 64 + hd4], h, l);
            *(float4*)&Vhs[key * 72 + hd4] = h;
            *(float4*)&Vls[key * 72 + hd4] = l;
        }
        __syncthreads();

        if (k0 <= qrow0 + 15) {             // warp has unmasked keys here
            // ---- S = Q K^T ----
            float S[8][4] = {};
#pragma unroll
            for (int n = 0; n < 8; n++) {
#pragma unroll
                for (int s = 0; s < 8; s++) {
                    unsigned b0h = fau(Khs[(n * 8 + g) * 68 + s * 8 + t]);
                    unsigned b1h = fau(Khs[(n * 8 + g) * 68 + s * 8 + t + 4]);
                    unsigned b0l = fau(Kls[(n * 8 + g) * 68 + s * 8 + t]);
                    unsigned b1l = fau(Kls[(n * 8 + g) * 68 + s * 8 + t + 4]);
                    mma_tf32(S[n], qh[s], b0h, b1h);
                    mma_tf32(S[n], ql[s], b0h, b1h);
                    mma_tf32(S[n], qh[s], b0l, b1l);
                }
            }
            // ---- causal mask ----
            if (k0 + 63 > qrow0) {
                int r0 = qrow0 + g, r1 = r0 + 8;
#pragma unroll
                for (int n = 0; n < 8; n++) {
                    int cb = k0 + n * 8 + 2 * t;
                    if (cb > r0)     S[n][0] = -1e30f;
                    if (cb + 1 > r0) S[n][1] = -1e30f;
                    if (cb > r1)     S[n][2] = -1e30f;
                    if (cb + 1 > r1) S[n][3] = -1e30f;
                }
            }
            // ---- online softmax (rows g, g+8; quad shfl reduce over t) ----
            float mx0 = -1e30f, mx1 = -1e30f;
#pragma unroll
            for (int n = 0; n < 8; n++) {
                mx0 = fmaxf(mx0, fmaxf(S[n][0], S[n][1]));
                mx1 = fmaxf(mx1, fmaxf(S[n][2], S[n][3]));
            }
            mx0 = fmaxf(mx0, __shfl_xor_sync(0xffffffffu, mx0, 1));
            mx0 = fmaxf(mx0, __shfl_xor_sync(0xffffffffu, mx0, 2));
            mx1 = fmaxf(mx1, __shfl_xor_sync(0xffffffffu, mx1, 1));
            mx1 = fmaxf(mx1, __shfl_xor_sync(0xffffffffu, mx1, 2));
            float mn0 = fmaxf(m0s, mx0), mn1 = fmaxf(m1s, mx1);
            float cr0 = __expf(m0s - mn0), cr1 = __expf(m1s - mn1);
            m0s = mn0; m1s = mn1;
            float rs0 = 0.f, rs1 = 0.f;
#pragma unroll
            for (int n = 0; n < 8; n++) {
                S[n][0] = __expf(S[n][0] - mn0);
                S[n][1] = __expf(S[n][1] - mn0);
                S[n][2] = __expf(S[n][2] - mn1);
                S[n][3] = __expf(S[n][3] - mn1);
                rs0 += S[n][0] + S[n][1];
                rs1 += S[n][2] + S[n][3];
            }
            rs0 += __shfl_xor_sync(0xffffffffu, rs0, 1);
            rs0 += __shfl_xor_sync(0xffffffffu, rs0, 2);
            rs1 += __shfl_xor_sync(0xffffffffu, rs1, 1);
            rs1 += __shfl_xor_sync(0xffffffffu, rs1, 2);
            l0s = l0s * cr0 + rs0;
            l1s = l1s * cr1 + rs1;
#pragma unroll
            for (int n = 0; n < 8; n++) {
                O[n][0] *= cr0; O[n][1] *= cr0;
                O[n][2] *= cr1; O[n][3] *= cr1;
            }
            // ---- P -> per-warp smem slabs, hi/lo pre-split ----
#pragma unroll
            for (int n = 0; n < 8; n++) {
                float h0 = uaf(f2tf(S[n][0])), l0 = uaf(f2tf(S[n][0] - h0));
                float h1 = uaf(f2tf(S[n][1])), l1 = uaf(f2tf(S[n][1] - h1));
                float h2 = uaf(f2tf(S[n][2])), l2 = uaf(f2tf(S[n][2] - h2));
                float h3 = uaf(f2tf(S[n][3])), l3 = uaf(f2tf(S[n][3] - h3));
                *(float2*)&Phs[(w * 16 + g) * 68 + n * 8 + 2 * t] = make_float2(h0, h1);
                *(float2*)&Pls[(w * 16 + g) * 68 + n * 8 + 2 * t] = make_float2(l0, l1);
                *(float2*)&Phs[(w * 16 + g + 8) * 68 + n * 8 + 2 * t] = make_float2(h2, h3);
                *(float2*)&Pls[(w * 16 + g + 8) * 68 + n * 8 + 2 * t] = make_float2(l2, l3);
            }
            __syncwarp();
            // ---- O += P V ----
#pragma unroll
            for (int s = 0; s < 8; s++) {
                unsigned pah[4], pal[4];
                pah[0] = fau(Phs[(w * 16 + g) * 68 + s * 8 + t]);
                pah[1] = fau(Phs[(w * 16 + g + 8) * 68 + s * 8 + t]);
                pah[2] = fau(Phs[(w * 16 + g) * 68 + s * 8 + t + 4]);
                pah[3] = fau(Phs[(w * 16 + g + 8) * 68 + s * 8 + t + 4]);
                pal[0] = fau(Pls[(w * 16 + g) * 68 + s * 8 + t]);
                pal[1] = fau(Pls[(w * 16 + g + 8) * 68 + s * 8 + t]);
                pal[2] = fau(Pls[(w * 16 + g) * 68 + s * 8 + t + 4]);
                pal[3] = fau(Pls[(w * 16 + g + 8) * 68 + s * 8 + t + 4]);
#pragma unroll
                for (int n = 0; n < 8; n++) {
                    unsigned b0h = fau(Vhs[(s * 8 + t) * 72 + n * 8 + g]);
                    unsigned b1h = fau(Vhs[(s * 8 + t + 4) * 72 + n * 8 + g]);
                    unsigned b0l = fau(Vls[(s * 8 + t) * 72 + n * 8 + g]);
                    unsigned b1l = fau(Vls[(s * 8 + t + 4) * 72 + n * 8 + g]);
                    mma_tf32(O[n], pah, b0h, b1h);
                    mma_tf32(O[n], pal, b0h, b1h);
                    mma_tf32(O[n], pah, b0l, b1l);
                }
            }
        }
    }

    // epilogue: y[B,T,C] for the proj GEMM
    const int b_ = bh_ / HH, h = bh_ % HH;
    const float inv0 = 1.f / l0s, inv1 = 1.f / l1s;
#pragma unroll
    for (int n = 0; n < 8; n++) {
        int col = h * 64 + n * 8 + 2 * t;
        int r0 = qrow0 + g;
        *(float2*)&g_y[((size_t)b_ * TT + r0) * CC + col] =
            make_float2(O[n][0] * inv0, O[n][1] * inv0);
        *(float2*)&g_y[((size_t)b_ * TT + r0 + 8) * CC + col] =
            make_float2(O[n][2] * inv1, O[n][3] * inv1);
    }
}

// ---------------------------------------------------------------------------
// Launch
// ---------------------------------------------------------------------------
static const int kGemmSmem = 4 * 128 * 36 * (int)sizeof(float);               // 73728
static const int kAttnSmem = (2 * 64 * 68 + 2 * 64 * 72 + 2 * 128 * 68) * (int)sizeof(float);

extern "C" void kernel_launch(void* const* d_in, const int* in_sizes, int n_in,
                              void* d_out, int out_size) {
    const float* x      = (const float*)d_in[0];
    const float* W_attn = (const float*)d_in[1];
    const float* b_attn = (const float*)d_in[2];
    const float* W_proj = (const float*)d_in[3];
    const float* b_proj = (const float*)d_in[4];
    float* out = (float*)d_out;

    cudaFuncSetAttribute(gemm_tc<true>,
                         cudaFuncAttributeMaxDynamicSharedMemorySize, kGemmSmem);
    cudaFuncSetAttribute(gemm_tc<false>,
                         cudaFuncAttributeMaxDynamicSharedMemorySize, kGemmSmem);
    cudaFuncSetAttribute(attn_tc,
                         cudaFuncAttributeMaxDynamicSharedMemorySize, kAttnSmem);

    // 1) qkv projection (scatter into per-head q/k/v)
    gemm_tc<true><<<dim3(NQKV / 128, MM / 128), 256, kGemmSmem>>>(
        x, W_attn, b_attn, nullptr, CC, NQKV);

    // 2) flash attention
    attn_tc<<<dim3(TT / 128, BB * HH), 256, kAttnSmem>>>();

    // 3) output projection
    gemm_tc<false><<<dim3(CC / 128, MM / 128), 256, kGemmSmem>>>(
        nullptr, W_proj, b_proj, out, CC, CC);
}

// round 5
// speedup vs baseline: 2.6325x; 1.4657x over previous
#include <cuda_runtime.h>
#include <cuda_bf16.h>
#include <math.h>

// Problem constants
#define BB 2
#define TT 2048
#define CC 1024
#define HH 16
#define HD 64
#define MM (BB*TT)        // 4096
#define NQKV (3*CC)       // 3072

// Scratch (device globals — allocation-free)
__device__ float g_q[(size_t)BB*HH*TT*HD];
__device__ float g_k[(size_t)BB*HH*TT*HD];
__device__ float g_v[(size_t)BB*HH*TT*HD];
__device__ float g_y[(size_t)BB*TT*CC];

// ---------------------------------------------------------------------------
// Helpers: bf16 packing + m16n8k16 bf16 mma, 2-way hi/lo error compensation.
// x = hi + lo with hi = bf16(x), lo = bf16(x - hi); products hh + lh + hl
// recover ~16 mantissa bits (lo*lo ~2^-18 dropped).
// ---------------------------------------------------------------------------
__device__ __forceinline__ unsigned bfhi2(float x, float y) {
    __nv_bfloat162 p = __floats2bfloat162_rn(x, y);
    return *(unsigned*)&p;
}
__device__ __forceinline__ unsigned bflo2(float x, float y) {
    float hx = __bfloat162float(__float2bfloat16_rn(x));
    float hy = __bfloat162float(__float2bfloat16_rn(y));
    return bfhi2(x - hx, y - hy);
}
__device__ __forceinline__ void split4bf(float4 v, uint2& h, uint2& l) {
    h.x = bfhi2(v.x, v.y); h.y = bfhi2(v.z, v.w);
    l.x = bflo2(v.x, v.y); l.y = bflo2(v.z, v.w);
}
__device__ __forceinline__ unsigned lds32(const __nv_bfloat16* p) {
    return *(const unsigned*)p;
}
__device__ __forceinline__ void mma_bf16(float d[4], const unsigned a[4],
                                         unsigned b0, unsigned b1) {
    asm volatile(
        "mma.sync.aligned.m16n8k16.row.col.f32.bf16.bf16.f32 "
        "{%0,%1,%2,%3}, {%4,%5,%6,%7}, {%8,%9}, {%0,%1,%2,%3};"
        : "+f"(d[0]), "+f"(d[1]), "+f"(d[2]), "+f"(d[3])
        : "r"(a[0]), "r"(a[1]), "r"(a[2]), "r"(a[3]), "r"(b0), "r"(b1));
}
__device__ __forceinline__ void ldmx2t(unsigned& r0, unsigned& r1, const void* p) {
    unsigned addr = (unsigned)__cvta_generic_to_shared(p);
    asm volatile("ldmatrix.sync.aligned.m8n8.x2.trans.shared.b16 {%0,%1}, [%2];"
                 : "=r"(r0), "=r"(r1) : "r"(addr));
}

// ---------------------------------------------------------------------------
// Tensor-core GEMM (bf16 x3): out[m,n] = sum_k A[m,k]*W[n,k] + bias[n]
// 128x128x32 tile, 512 threads = 16 warps (4x4), warp tile 32x32.
// bf16 hi/lo planes in smem (LDA=40 -> conflict-free fragment loads).
// Register double-buffer: LDG next tile while computing current.
// ---------------------------------------------------------------------------
template<bool QKV_SCATTER>
__global__ __launch_bounds__(512, 1)
void gemm_tc(const float* __restrict__ A, const float* __restrict__ W,
             const float* __restrict__ bias, float* __restrict__ Cout,
             int K, int N) {
    constexpr int BM = 128, BK = 32, LDA = 40;
    __shared__ __nv_bfloat16 Ah[BM * LDA], Al[BM * LDA];
    __shared__ __nv_bfloat16 Wh[BM * LDA], Wl[BM * LDA];

    const float* Ap = A ? A : g_y;

    const int tid = threadIdx.x;
    const int lane = tid & 31, w = tid >> 5;
    const int g = lane >> 2, t = lane & 3;
    const int m0 = blockIdx.y * BM, n0 = blockIdx.x * BM;
    const int wm = (w >> 2) * 32;
    const int wn = (w & 3) * 32;

    const int lrow = tid >> 3;              // 0..63 (+64*i)
    const int lcol = (tid & 7) * 4;         // 0..28

    float acc[2][4][4] = {};

    float4 ra[2], rw[2];
#pragma unroll
    for (int i = 0; i < 2; i++) {
        int row = lrow + 64 * i;
        ra[i] = *(const float4*)&Ap[(size_t)(m0 + row) * K + lcol];
        rw[i] = *(const float4*)&W[(size_t)(n0 + row) * K + lcol];
    }

    for (int kt = 0; kt < K; kt += BK) {
        __syncthreads();
#pragma unroll
        for (int i = 0; i < 2; i++) {
            int row = lrow + 64 * i;
            uint2 h, l;
            split4bf(ra[i], h, l);
            *(uint2*)&Ah[row * LDA + lcol] = h;
            *(uint2*)&Al[row * LDA + lcol] = l;
            split4bf(rw[i], h, l);
            *(uint2*)&Wh[row * LDA + lcol] = h;
            *(uint2*)&Wl[row * LDA + lcol] = l;
        }
        if (kt + BK < K) {
#pragma unroll
            for (int i = 0; i < 2; i++) {
                int row = lrow + 64 * i;
                ra[i] = *(const float4*)&Ap[(size_t)(m0 + row) * K + kt + BK + lcol];
                rw[i] = *(const float4*)&W[(size_t)(n0 + row) * K + kt + BK + lcol];
            }
        }
        __syncthreads();

#pragma unroll
        for (int s = 0; s < 2; s++) {       // two k16 slices
            const int kc = s * 16 + 2 * t;
            unsigned ah[2][4], al[2][4];
#pragma unroll
            for (int mi = 0; mi < 2; mi++) {
                const int r = wm + mi * 16 + g;
                ah[mi][0] = lds32(&Ah[r * LDA + kc]);
                ah[mi][1] = lds32(&Ah[(r + 8) * LDA + kc]);
                ah[mi][2] = lds32(&Ah[r * LDA + kc + 8]);
                ah[mi][3] = lds32(&Ah[(r + 8) * LDA + kc + 8]);
                al[mi][0] = lds32(&Al[r * LDA + kc]);
                al[mi][1] = lds32(&Al[(r + 8) * LDA + kc]);
                al[mi][2] = lds32(&Al[r * LDA + kc + 8]);
                al[mi][3] = lds32(&Al[(r + 8) * LDA + kc + 8]);
            }
            unsigned bh[4][2], bl[4][2];
#pragma unroll
            for (int ni = 0; ni < 4; ni++) {
                const int c0 = wn + ni * 8 + g;
                bh[ni][0] = lds32(&Wh[c0 * LDA + kc]);
                bh[ni][1] = lds32(&Wh[c0 * LDA + kc + 8]);
                bl[ni][0] = lds32(&Wl[c0 * LDA + kc]);
                bl[ni][1] = lds32(&Wl[c0 * LDA + kc + 8]);
            }
#pragma unroll
            for (int mi = 0; mi < 2; mi++)
#pragma unroll
                for (int ni = 0; ni < 4; ni++) {
                    mma_bf16(acc[mi][ni], ah[mi], bh[ni][0], bh[ni][1]);
                    mma_bf16(acc[mi][ni], al[mi], bh[ni][0], bh[ni][1]);
                    mma_bf16(acc[mi][ni], ah[mi], bl[ni][0], bl[ni][1]);
                }
        }
    }

    // epilogue
#pragma unroll
    for (int mi = 0; mi < 2; mi++)
#pragma unroll
        for (int ni = 0; ni < 4; ni++)
#pragma unroll
            for (int e = 0; e < 4; e++) {
                int row = m0 + wm + mi * 16 + g + ((e >= 2) ? 8 : 0);
                int col = n0 + wn + ni * 8 + 2 * t + (e & 1);
                float v = acc[mi][ni][e] + __ldg(&bias[col]);
                if (QKV_SCATTER) {
                    int which = col >> 10;          // 0=q,1=k,2=v
                    int c = col & (CC - 1);
                    int h = c >> 6, d = c & 63;
                    int b_ = row >> 11;
                    int tt = row & (TT - 1);
                    size_t dst = (((size_t)(b_ * HH + h) * TT + tt) * HD) + d;
                    float* base = (which == 0) ? g_q : ((which == 1) ? g_k : g_v);
                    base[dst] = v;
                } else {
                    Cout[(size_t)row * N + col] = v;
                }
            }
}

// ---------------------------------------------------------------------------
// Tensor-core flash attention (bf16 x3).
// grid = (T/256, B*H), 512 threads = 16 warps; warp w owns q-rows [16w,16w+16).
// K/V 64-key tiles as bf16 hi/lo planes (LD=72, conflict-free); V fragments
// via ldmatrix.x2.trans; P bf16 hi/lo via per-warp smem round-trip.
// ---------------------------------------------------------------------------
__global__ __launch_bounds__(512, 1)
void attn_tc() {
    constexpr int LD = 72;
    extern __shared__ __nv_bfloat16 smb[];
    __nv_bfloat16* Khs = smb;                  // [64][72]
    __nv_bfloat16* Kls = Khs + 64 * LD;
    __nv_bfloat16* Vhs = Kls + 64 * LD;        // [64][72]
    __nv_bfloat16* Vls = Vhs + 64 * LD;
    __nv_bfloat16* Phs = Vls + 64 * LD;        // [256][72]
    __nv_bfloat16* Pls = Phs + 256 * LD;

    const int tid = threadIdx.x;
    const int lane = tid & 31, w = tid >> 5;
    const int g = lane >> 2, t = lane & 3;
    const int qi = (int)gridDim.x - 1 - (int)blockIdx.x;  // big tiles first
    const int bh_ = blockIdx.y;

    const float* Qg = g_q + (size_t)bh_ * TT * HD;
    const float* Kg = g_k + (size_t)bh_ * TT * HD;
    const float* Vg = g_v + (size_t)bh_ * TT * HD;

    const int qrow0 = qi * 256 + w * 16;

    // Q fragments (scaled by 1/8, exact), bf16 hi/lo, registers
    unsigned qh[4][4], ql[4][4];
#pragma unroll
    for (int s = 0; s < 4; s++) {
        const int c0 = s * 16 + 2 * t;
        float2 x00 = *(const float2*)&Qg[(size_t)(qrow0 + g) * 64 + c0];
        float2 x01 = *(const float2*)&Qg[(size_t)(qrow0 + g) * 64 + c0 + 8];
        float2 x10 = *(const float2*)&Qg[(size_t)(qrow0 + g + 8) * 64 + c0];
        float2 x11 = *(const float2*)&Qg[(size_t)(qrow0 + g + 8) * 64 + c0 + 8];
        x00.x *= 0.125f; x00.y *= 0.125f; x01.x *= 0.125f; x01.y *= 0.125f;
        x10.x *= 0.125f; x10.y *= 0.125f; x11.x *= 0.125f; x11.y *= 0.125f;
        qh[s][0] = bfhi2(x00.x, x00.y); ql[s][0] = bflo2(x00.x, x00.y);
        qh[s][1] = bfhi2(x10.x, x10.y); ql[s][1] = bflo2(x10.x, x10.y);
        qh[s][2] = bfhi2(x01.x, x01.y); ql[s][2] = bflo2(x01.x, x01.y);
        qh[s][3] = bfhi2(x11.x, x11.y); ql[s][3] = bflo2(x11.x, x11.y);
    }

    float m0s = -1e30f, m1s = -1e30f, l0s = 0.f, l1s = 0.f;
    float O[8][4] = {};

    const int nkb = 4 * qi + 4;
    for (int kb = 0; kb < nkb; kb++) {
        const int k0 = kb * 64;
        __syncthreads();
        // cooperative K/V tile load + bf16 hi/lo split
#pragma unroll
        for (int i = 0; i < 2; i++) {
            int c = tid + 512 * i;
            int key = c >> 4, hd4 = (c & 15) * 4;
            uint2 h, l;
            split4bf(*(const float4*)&Kg[(size_t)(k0 + key) * 64 + hd4], h, l);
            *(uint2*)&Khs[key * LD + hd4] = h;
            *(uint2*)&Kls[key * LD + hd4] = l;
            split4bf(*(const float4*)&Vg[(size_t)(k0 + key) * 64 + hd4], h, l);
            *(uint2*)&Vhs[key * LD + hd4] = h;
            *(uint2*)&Vls[key * LD + hd4] = l;
        }
        __syncthreads();

        if (k0 <= qrow0 + 15) {             // warp has unmasked keys here
            // ---- S = Q K^T ----
            float S[8][4] = {};
#pragma unroll
            for (int n = 0; n < 8; n++) {
                const int kr = (n * 8 + g) * LD;
#pragma unroll
                for (int s = 0; s < 4; s++) {
                    const int kc = s * 16 + 2 * t;
                    unsigned b0h = lds32(&Khs[kr + kc]);
                    unsigned b1h = lds32(&Khs[kr + kc + 8]);
                    unsigned b0l = lds32(&Kls[kr + kc]);
                    unsigned b1l = lds32(&Kls[kr + kc + 8]);
                    mma_bf16(S[n], qh[s], b0h, b1h);
                    mma_bf16(S[n], ql[s], b0h, b1h);
                    mma_bf16(S[n], qh[s], b0l, b1l);
                }
            }
            // ---- causal mask ----
            if (k0 + 63 > qrow0) {
                int r0 = qrow0 + g, r1 = r0 + 8;
#pragma unroll
                for (int n = 0; n < 8; n++) {
                    int cb = k0 + n * 8 + 2 * t;
                    if (cb > r0)     S[n][0] = -1e30f;
                    if (cb + 1 > r0) S[n][1] = -1e30f;
                    if (cb > r1)     S[n][2] = -1e30f;
                    if (cb + 1 > r1) S[n][3] = -1e30f;
                }
            }
            // ---- online softmax (rows g, g+8; quad shfl reduce over t) ----
            float mx0 = -1e30f, mx1 = -1e30f;
#pragma unroll
            for (int n = 0; n < 8; n++) {
                mx0 = fmaxf(mx0, fmaxf(S[n][0], S[n][1]));
                mx1 = fmaxf(mx1, fmaxf(S[n][2], S[n][3]));
            }
            mx0 = fmaxf(mx0, __shfl_xor_sync(0xffffffffu, mx0, 1));
            mx0 = fmaxf(mx0, __shfl_xor_sync(0xffffffffu, mx0, 2));
            mx1 = fmaxf(mx1, __shfl_xor_sync(0xffffffffu, mx1, 1));
            mx1 = fmaxf(mx1, __shfl_xor_sync(0xffffffffu, mx1, 2));
            float mn0 = fmaxf(m0s, mx0), mn1 = fmaxf(m1s, mx1);
            float cr0 = __expf(m0s - mn0), cr1 = __expf(m1s - mn1);
            m0s = mn0; m1s = mn1;
            float rs0 = 0.f, rs1 = 0.f;
#pragma unroll
            for (int n = 0; n < 8; n++) {
                S[n][0] = __expf(S[n][0] - mn0);
                S[n][1] = __expf(S[n][1] - mn0);
                S[n][2] = __expf(S[n][2] - mn1);
                S[n][3] = __expf(S[n][3] - mn1);
                rs0 += S[n][0] + S[n][1];
                rs1 += S[n][2] + S[n][3];
            }
            rs0 += __shfl_xor_sync(0xffffffffu, rs0, 1);
            rs0 += __shfl_xor_sync(0xffffffffu, rs0, 2);
            rs1 += __shfl_xor_sync(0xffffffffu, rs1, 1);
            rs1 += __shfl_xor_sync(0xffffffffu, rs1, 2);
            l0s = l0s * cr0 + rs0;
            l1s = l1s * cr1 + rs1;
#pragma unroll
            for (int n = 0; n < 8; n++) {
                O[n][0] *= cr0; O[n][1] *= cr0;
                O[n][2] *= cr1; O[n][3] *= cr1;
            }
            // ---- P -> per-warp smem slabs, bf16 hi/lo ----
            const int pr0 = (w * 16 + g) * LD, pr1 = pr0 + 8 * LD;
#pragma unroll
            for (int n = 0; n < 8; n++) {
                const int pc = n * 8 + 2 * t;
                *(unsigned*)&Phs[pr0 + pc] = bfhi2(S[n][0], S[n][1]);
                *(unsigned*)&Pls[pr0 + pc] = bflo2(S[n][0], S[n][1]);
                *(unsigned*)&Phs[pr1 + pc] = bfhi2(S[n][2], S[n][3]);
                *(unsigned*)&Pls[pr1 + pc] = bflo2(S[n][2], S[n][3]);
            }
            __syncwarp();
            // ---- O += P V ----
            const int rsel = lane & 15;      // ldmatrix row provider
#pragma unroll
            for (int s = 0; s < 4; s++) {
                const int kc = s * 16 + 2 * t;
                unsigned pah[4], pal[4];
                pah[0] = lds32(&Phs[pr0 + kc]);
                pah[1] = lds32(&Phs[pr1 + kc]);
                pah[2] = lds32(&Phs[pr0 + kc + 8]);
                pah[3] = lds32(&Phs[pr1 + kc + 8]);
                pal[0] = lds32(&Pls[pr0 + kc]);
                pal[1] = lds32(&Pls[pr1 + kc]);
                pal[2] = lds32(&Pls[pr0 + kc + 8]);
                pal[3] = lds32(&Pls[pr1 + kc + 8]);
                const __nv_bfloat16* vrow_h = &Vhs[(s * 16 + rsel) * LD];
                const __nv_bfloat16* vrow_l = &Vls[(s * 16 + rsel) * LD];
#pragma unroll
                for (int n = 0; n < 8; n++) {
                    unsigned vh0, vh1, vl0, vl1;
                    ldmx2t(vh0, vh1, vrow_h + n * 8);
                    ldmx2t(vl0, vl1, vrow_l + n * 8);
                    mma_bf16(O[n], pah, vh0, vh1);
                    mma_bf16(O[n], pal, vh0, vh1);
                    mma_bf16(O[n], pah, vl0, vl1);
                }
            }
        }
    }

    // epilogue: y[B,T,C] for the proj GEMM
    const int b_ = bh_ / HH, h = bh_ % HH;
    const float inv0 = 1.f / l0s, inv1 = 1.f / l1s;
#pragma unroll
    for (int n = 0; n < 8; n++) {
        int col = h * 64 + n * 8 + 2 * t;
        int r0 = qrow0 + g;
        *(float2*)&g_y[((size_t)b_ * TT + r0) * CC + col] =
            make_float2(O[n][0] * inv0, O[n][1] * inv0);
        *(float2*)&g_y[((size_t)b_ * TT + r0 + 8) * CC + col] =
            make_float2(O[n][2] * inv1, O[n][3] * inv1);
    }
}

// ---------------------------------------------------------------------------
// Launch
// ---------------------------------------------------------------------------
static const int kAttnSmem = (4 * 64 * 72 + 2 * 256 * 72) * 2;   // 110592 B

extern "C" void kernel_launch(void* const* d_in, const int* in_sizes, int n_in,
                              void* d_out, int out_size) {
    const float* x      = (const float*)d_in[0];
    const float* W_attn = (const float*)d_in[1];
    const float* b_attn = (const float*)d_in[2];
    const float* W_proj = (const float*)d_in[3];
    const float* b_proj = (const float*)d_in[4];
    float* out = (float*)d_out;

    cudaFuncSetAttribute(attn_tc,
                         cudaFuncAttributeMaxDynamicSharedMemorySize, kAttnSmem);

    // 1) qkv projection (scatter into per-head q/k/v)
    gemm_tc<true><<<dim3(NQKV / 128, MM / 128), 512>>>(
        x, W_attn, b_attn, nullptr, CC, NQKV);

    // 2) flash attention
    attn_tc<<<dim3(TT / 256, BB * HH), 512, kAttnSmem>>>();

    // 3) output projection
    gemm_tc<false><<<dim3(CC / 128, MM / 128), 512>>>(
        nullptr, W_proj, b_proj, out, CC, CC);
}

// round 8
// speedup vs baseline: 2.7688x; 1.0518x over previous
#include <cuda_runtime.h>
#include <cuda_bf16.h>
#include <math.h>

// Problem constants
#define BB 2
#define TT 2048
#define CC 1024
#define HH 16
#define HD 64
#define MM (BB*TT)        // 4096
#define NQKV (3*CC)       // 3072

// Scratch (device globals — allocation-free)
__device__ float g_q[(size_t)BB*HH*TT*HD];
__device__ float g_k[(size_t)BB*HH*TT*HD];
__device__ float g_v[(size_t)BB*HH*TT*HD];
__device__ float g_y[(size_t)BB*TT*CC];

// ---------------------------------------------------------------------------
// Helpers: bf16 packing + m16n8k16 bf16 mma, 2-way hi/lo error compensation.
// ---------------------------------------------------------------------------
__device__ __forceinline__ unsigned bfhi2(float x, float y) {
    __nv_bfloat162 p = __floats2bfloat162_rn(x, y);
    return *(unsigned*)&p;
}
__device__ __forceinline__ unsigned bflo2(float x, float y) {
    float hx = __bfloat162float(__float2bfloat16_rn(x));
    float hy = __bfloat162float(__float2bfloat16_rn(y));
    return bfhi2(x - hx, y - hy);
}
__device__ __forceinline__ void split4bf(float4 v, uint2& h, uint2& l) {
    h.x = bfhi2(v.x, v.y); h.y = bfhi2(v.z, v.w);
    l.x = bflo2(v.x, v.y); l.y = bflo2(v.z, v.w);
}
__device__ __forceinline__ void mma_bf16(float d[4], const unsigned a[4],
                                         unsigned b0, unsigned b1) {
    asm volatile(
        "mma.sync.aligned.m16n8k16.row.col.f32.bf16.bf16.f32 "
        "{%0,%1,%2,%3}, {%4,%5,%6,%7}, {%8,%9}, {%0,%1,%2,%3};"
        : "+f"(d[0]), "+f"(d[1]), "+f"(d[2]), "+f"(d[3])
        : "r"(a[0]), "r"(a[1]), "r"(a[2]), "r"(a[3]), "r"(b0), "r"(b1));
}
__device__ __forceinline__ void ldmx4(unsigned r[4], const void* p) {
    unsigned addr = (unsigned)__cvta_generic_to_shared(p);
    asm volatile("ldmatrix.sync.aligned.m8n8.x4.shared.b16 {%0,%1,%2,%3}, [%4];"
                 : "=r"(r[0]), "=r"(r[1]), "=r"(r[2]), "=r"(r[3]) : "r"(addr));
}
__device__ __forceinline__ void ldmx2t(unsigned& r0, unsigned& r1, const void* p) {
    unsigned addr = (unsigned)__cvta_generic_to_shared(p);
    asm volatile("ldmatrix.sync.aligned.m8n8.x2.trans.shared.b16 {%0,%1}, [%2];"
                 : "=r"(r0), "=r"(r1) : "r"(addr));
}

// ---------------------------------------------------------------------------
// Tensor-core GEMM (bf16 x3): out[m,n] = sum_k A[m,k]*W[n,k] + bias[n]
// 128x128x32 tile, 512 threads = 16 warps (4x4), warp tile 32x32.
// ldmatrix.x4 fragment loads; product-major MMA ordering (8 indep accs).
// ---------------------------------------------------------------------------
template<bool QKV_SCATTER>
__global__ __launch_bounds__(512, 1)
void gemm_tc(const float* __restrict__ A, const float* __restrict__ W,
             const float* __restrict__ bias, float* __restrict__ Cout,
             int K, int N) {
    constexpr int BM = 128, BK = 32, LDA = 40;
    __shared__ __nv_bfloat16 Ah[BM * LDA], Al[BM * LDA];
    __shared__ __nv_bfloat16 Wh[BM * LDA], Wl[BM * LDA];

    const float* Ap = A ? A : g_y;

    const int tid = threadIdx.x;
    const int lane = tid & 31, w = tid >> 5;
    const int g = lane >> 2, t = lane & 3;
    const int m0 = blockIdx.y * BM, n0 = blockIdx.x * BM;
    const int wm = (w >> 2) * 32;
    const int wn = (w & 3) * 32;

    const int lrow = tid >> 3;              // 0..63 (+64*i)
    const int lcol = (tid & 7) * 4;         // 0..28

    // ldmatrix lane-address components
    const int arow = lane & 15;             // A/x4: row within 16
    const int acol8 = (lane >> 4) << 3;     // A/x4: col +8 for upper half
    const int brow = (lane & 7) + ((lane >> 4) << 3);  // B/x4 row
    const int bcol8 = lane & 8;             // B/x4 col +8

    float acc[2][4][4] = {};

    float4 ra[2], rw[2];
#pragma unroll
    for (int i = 0; i < 2; i++) {
        int row = lrow + 64 * i;
        ra[i] = *(const float4*)&Ap[(size_t)(m0 + row) * K + lcol];
        rw[i] = *(const float4*)&W[(size_t)(n0 + row) * K + lcol];
    }

    for (int kt = 0; kt < K; kt += BK) {
        __syncthreads();
#pragma unroll
        for (int i = 0; i < 2; i++) {
            int row = lrow + 64 * i;
            uint2 h, l;
            split4bf(ra[i], h, l);
            *(uint2*)&Ah[row * LDA + lcol] = h;
            *(uint2*)&Al[row * LDA + lcol] = l;
            split4bf(rw[i], h, l);
            *(uint2*)&Wh[row * LDA + lcol] = h;
            *(uint2*)&Wl[row * LDA + lcol] = l;
        }
        if (kt + BK < K) {
#pragma unroll
            for (int i = 0; i < 2; i++) {
                int row = lrow + 64 * i;
                ra[i] = *(const float4*)&Ap[(size_t)(m0 + row) * K + kt + BK + lcol];
                rw[i] = *(const float4*)&W[(size_t)(n0 + row) * K + kt + BK + lcol];
            }
        }
        __syncthreads();

#pragma unroll
        for (int s = 0; s < 2; s++) {       // two k16 slices
            const int kc0 = s * 16;
            unsigned ah[2][4], al[2][4];
            ldmx4(ah[0], &Ah[(wm + arow) * LDA + kc0 + acol8]);
            ldmx4(ah[1], &Ah[(wm + 16 + arow) * LDA + kc0 + acol8]);
            ldmx4(al[0], &Al[(wm + arow) * LDA + kc0 + acol8]);
            ldmx4(al[1], &Al[(wm + 16 + arow) * LDA + kc0 + acol8]);
            unsigned bh[4][2], bl[4][2];
            {
                unsigned t0[4], t1[4];
                ldmx4(t0, &Wh[(wn + brow) * LDA + kc0 + bcol8]);
                ldmx4(t1, &Wh[(wn + 16 + brow) * LDA + kc0 + bcol8]);
                bh[0][0] = t0[0]; bh[0][1] = t0[1]; bh[1][0] = t0[2]; bh[1][1] = t0[3];
                bh[2][0] = t1[0]; bh[2][1] = t1[1]; bh[3][0] = t1[2]; bh[3][1] = t1[3];
                ldmx4(t0, &Wl[(wn + brow) * LDA + kc0 + bcol8]);
                ldmx4(t1, &Wl[(wn + 16 + brow) * LDA + kc0 + bcol8]);
                bl[0][0] = t0[0]; bl[0][1] = t0[1]; bl[1][0] = t0[2]; bl[1][1] = t0[3];
                bl[2][0] = t1[0]; bl[2][1] = t1[1]; bl[3][0] = t1[2]; bl[3][1] = t1[3];
            }
            // product-major: all 8 accumulators per product
#pragma unroll
            for (int mi = 0; mi < 2; mi++)
#pragma unroll
                for (int ni = 0; ni < 4; ni++)
                    mma_bf16(acc[mi][ni], ah[mi], bh[ni][0], bh[ni][1]);
#pragma unroll
            for (int mi = 0; mi < 2; mi++)
#pragma unroll
                for (int ni = 0; ni < 4; ni++)
                    mma_bf16(acc[mi][ni], al[mi], bh[ni][0], bh[ni][1]);
#pragma unroll
            for (int mi = 0; mi < 2; mi++)
#pragma unroll
                for (int ni = 0; ni < 4; ni++)
                    mma_bf16(acc[mi][ni], ah[mi], bl[ni][0], bl[ni][1]);
        }
    }

    // epilogue
#pragma unroll
    for (int mi = 0; mi < 2; mi++)
#pragma unroll
        for (int ni = 0; ni < 4; ni++)
#pragma unroll
            for (int e = 0; e < 4; e++) {
                int row = m0 + wm + mi * 16 + g + ((e >= 2) ? 8 : 0);
                int col = n0 + wn + ni * 8 + 2 * t + (e & 1);
                float v = acc[mi][ni][e] + __ldg(&bias[col]);
                if (QKV_SCATTER) {
                    int which = col >> 10;          // 0=q,1=k,2=v
                    int c = col & (CC - 1);
                    int h = c >> 6, d = c & 63;
                    int b_ = row >> 11;
                    int tt = row & (TT - 1);
                    size_t dst = (((size_t)(b_ * HH + h) * TT + tt) * HD) + d;
                    float* base = (which == 0) ? g_q : ((which == 1) ? g_k : g_v);
                    base[dst] = v;
                } else {
                    Cout[(size_t)row * N + col] = v;
                }
            }
}

// ---------------------------------------------------------------------------
// Tensor-core flash attention (bf16 x3), ldmatrix frags, product-major MMAs.
// grid = (T/256, B*H), 512 threads = 16 warps; warp w owns q-rows [16w,16w+16).
// ---------------------------------------------------------------------------
__global__ __launch_bounds__(512, 1)
void attn_tc() {
    constexpr int LD = 72;
    extern __shared__ __nv_bfloat16 smb[];
    __nv_bfloat16* Khs = smb;                  // [64][72]
    __nv_bfloat16* Kls = Khs + 64 * LD;
    __nv_bfloat16* Vhs = Kls + 64 * LD;        // [64][72]
    __nv_bfloat16* Vls = Vhs + 64 * LD;
    __nv_bfloat16* Phs = Vls + 64 * LD;        // [256][72]
    __nv_bfloat16* Pls = Phs + 256 * LD;

    const int tid = threadIdx.x;
    const int lane = tid & 31, w = tid >> 5;
    const int g = lane >> 2, t = lane & 3;
    const int qi = (int)gridDim.x - 1 - (int)blockIdx.x;  // big tiles first
    const int bh_ = blockIdx.y;

    const float* Qg = g_q + (size_t)bh_ * TT * HD;
    const float* Kg = g_k + (size_t)bh_ * TT * HD;
    const float* Vg = g_v + (size_t)bh_ * TT * HD;

    const int qrow0 = qi * 256 + w * 16;

    // ldmatrix lane-address components
    const int arow = lane & 15, acol8 = (lane >> 4) << 3;
    const int brow = (lane & 7) + ((lane >> 4) << 3), bcol8 = lane & 8;
    const int rsel = lane & 15;

    // Q fragments (scaled by 1/8, exact), bf16 hi/lo, registers
    unsigned qh[4][4], ql[4][4];
#pragma unroll
    for (int s = 0; s < 4; s++) {
        const int c0 = s * 16 + 2 * t;
        float2 x00 = *(const float2*)&Qg[(size_t)(qrow0 + g) * 64 + c0];
        float2 x01 = *(const float2*)&Qg[(size_t)(qrow0 + g) * 64 + c0 + 8];
        float2 x10 = *(const float2*)&Qg[(size_t)(qrow0 + g + 8) * 64 + c0];
        float2 x11 = *(const float2*)&Qg[(size_t)(qrow0 + g + 8) * 64 + c0 + 8];
        x00.x *= 0.125f; x00.y *= 0.125f; x01.x *= 0.125f; x01.y *= 0.125f;
        x10.x *= 0.125f; x10.y *= 0.125f; x11.x *= 0.125f; x11.y *= 0.125f;
        qh[s][0] = bfhi2(x00.x, x00.y); ql[s][0] = bflo2(x00.x, x00.y);
        qh[s][1] = bfhi2(x10.x, x10.y); ql[s][1] = bflo2(x10.x, x10.y);
        qh[s][2] = bfhi2(x01.x, x01.y); ql[s][2] = bflo2(x01.x, x01.y);
        qh[s][3] = bfhi2(x11.x, x11.y); ql[s][3] = bflo2(x11.x, x11.y);
    }

    float m0s = -1e30f, m1s = -1e30f, l0s = 0.f, l1s = 0.f;
    float O[8][4] = {};

    const int nkb = 4 * qi + 4;
    for (int kb = 0; kb < nkb; kb++) {
        const int k0 = kb * 64;
        __syncthreads();
        // cooperative K/V tile load + bf16 hi/lo split
#pragma unroll
        for (int i = 0; i < 2; i++) {
            int c = tid + 512 * i;
            int key = c >> 4, hd4 = (c & 15) * 4;
            uint2 h, l;
            split4bf(*(const float4*)&Kg[(size_t)(k0 + key) * 64 + hd4], h, l);
            *(uint2*)&Khs[key * LD + hd4] = h;
            *(uint2*)&Kls[key * LD + hd4] = l;
            split4bf(*(const float4*)&Vg[(size_t)(k0 + key) * 64 + hd4], h, l);
            *(uint2*)&Vhs[key * LD + hd4] = h;
            *(uint2*)&Vls[key * LD + hd4] = l;
        }
        __syncthreads();

        if (k0 <= qrow0 + 15) {             // warp has unmasked keys here
            // ---- S = Q K^T ----
            float S[8][4] = {};
#pragma unroll
            for (int s = 0; s < 4; s++) {
                const int kc0 = s * 16;
#pragma unroll
                for (int nh = 0; nh < 2; nh++) {
                    unsigned bh4[2][4], bl4[2][4];
                    const int kr = nh * 32 + brow;
                    ldmx4(bh4[0], &Khs[kr * LD + kc0 + bcol8]);
                    ldmx4(bh4[1], &Khs[(kr + 16) * LD + kc0 + bcol8]);
                    ldmx4(bl4[0], &Kls[kr * LD + kc0 + bcol8]);
                    ldmx4(bl4[1], &Kls[(kr + 16) * LD + kc0 + bcol8]);
                    // product-major over 4 independent accumulators
#pragma unroll
                    for (int j = 0; j < 4; j++)
                        mma_bf16(S[nh * 4 + j], qh[s],
                                 bh4[j >> 1][(j & 1) * 2], bh4[j >> 1][(j & 1) * 2 + 1]);
#pragma unroll
                    for (int j = 0; j < 4; j++)
                        mma_bf16(S[nh * 4 + j], ql[s],
                                 bh4[j >> 1][(j & 1) * 2], bh4[j >> 1][(j & 1) * 2 + 1]);
#pragma unroll
                    for (int j = 0; j < 4; j++)
                        mma_bf16(S[nh * 4 + j], qh[s],
                                 bl4[j >> 1][(j & 1) * 2], bl4[j >> 1][(j & 1) * 2 + 1]);
                }
            }
            // ---- causal mask ----
            if (k0 + 63 > qrow0) {
                int r0 = qrow0 + g, r1 = r0 + 8;
#pragma unroll
                for (int n = 0; n < 8; n++) {
                    int cb = k0 + n * 8 + 2 * t;
                    if (cb > r0)     S[n][0] = -1e30f;
                    if (cb + 1 > r0) S[n][1] = -1e30f;
                    if (cb > r1)     S[n][2] = -1e30f;
                    if (cb + 1 > r1) S[n][3] = -1e30f;
                }
            }
            // ---- online softmax (rows g, g+8; quad shfl reduce over t) ----
            float mx0 = -1e30f, mx1 = -1e30f;
#pragma unroll
            for (int n = 0; n < 8; n++) {
                mx0 = fmaxf(mx0, fmaxf(S[n][0], S[n][1]));
                mx1 = fmaxf(mx1, fmaxf(S[n][2], S[n][3]));
            }
            mx0 = fmaxf(mx0, __shfl_xor_sync(0xffffffffu, mx0, 1));
            mx0 = fmaxf(mx0, __shfl_xor_sync(0xffffffffu, mx0, 2));
            mx1 = fmaxf(mx1, __shfl_xor_sync(0xffffffffu, mx1, 1));
            mx1 = fmaxf(mx1, __shfl_xor_sync(0xffffffffu, mx1, 2));
            float mn0 = fmaxf(m0s, mx0), mn1 = fmaxf(m1s, mx1);
            float cr0 = __expf(m0s - mn0), cr1 = __expf(m1s - mn1);
            m0s = mn0; m1s = mn1;
            float rs0 = 0.f, rs1 = 0.f;
#pragma unroll
            for (int n = 0; n < 8; n++) {
                S[n][0] = __expf(S[n][0] - mn0);
                S[n][1] = __expf(S[n][1] - mn0);
                S[n][2] = __expf(S[n][2] - mn1);
                S[n][3] = __expf(S[n][3] - mn1);
                rs0 += S[n][0] + S[n][1];
                rs1 += S[n][2] + S[n][3];
            }
            rs0 += __shfl_xor_sync(0xffffffffu, rs0, 1);
            rs0 += __shfl_xor_sync(0xffffffffu, rs0, 2);
            rs1 += __shfl_xor_sync(0xffffffffu, rs1, 1);
            rs1 += __shfl_xor_sync(0xffffffffu, rs1, 2);
            l0s = l0s * cr0 + rs0;
            l1s = l1s * cr1 + rs1;
#pragma unroll
            for (int n = 0; n < 8; n++) {
                O[n][0] *= cr0; O[n][1] *= cr0;
                O[n][2] *= cr1; O[n][3] *= cr1;
            }
            // ---- P -> per-warp smem slabs, bf16 hi/lo ----
            const int pr0 = (w * 16 + g) * LD, pr1 = pr0 + 8 * LD;
#pragma unroll
            for (int n = 0; n < 8; n++) {
                const int pc = n * 8 + 2 * t;
                *(unsigned*)&Phs[pr0 + pc] = bfhi2(S[n][0], S[n][1]);
                *(unsigned*)&Pls[pr0 + pc] = bflo2(S[n][0], S[n][1]);
                *(unsigned*)&Phs[pr1 + pc] = bfhi2(S[n][2], S[n][3]);
                *(unsigned*)&Pls[pr1 + pc] = bflo2(S[n][2], S[n][3]);
            }
            __syncwarp();
            // ---- O += P V ----
#pragma unroll
            for (int s = 0; s < 4; s++) {
                unsigned pah[4], pal[4];
                ldmx4(pah, &Phs[(w * 16 + arow) * LD + s * 16 + acol8]);
                ldmx4(pal, &Pls[(w * 16 + arow) * LD + s * 16 + acol8]);
                const __nv_bfloat16* vrow_h = &Vhs[(s * 16 + rsel) * LD];
                const __nv_bfloat16* vrow_l = &Vls[(s * 16 + rsel) * LD];
#pragma unroll
                for (int nh = 0; nh < 2; nh++) {
                    unsigned vh[4][2], vl[4][2];
#pragma unroll
                    for (int j = 0; j < 4; j++) {
                        ldmx2t(vh[j][0], vh[j][1], vrow_h + (nh * 4 + j) * 8);
                        ldmx2t(vl[j][0], vl[j][1], vrow_l + (nh * 4 + j) * 8);
                    }
#pragma unroll
                    for (int j = 0; j < 4; j++)
                        mma_bf16(O[nh * 4 + j], pah, vh[j][0], vh[j][1]);
#pragma unroll
                    for (int j = 0; j < 4; j++)
                        mma_bf16(O[nh * 4 + j], pal, vh[j][0], vh[j][1]);
#pragma unroll
                    for (int j = 0; j < 4; j++)
                        mma_bf16(O[nh * 4 + j], pah, vl[j][0], vl[j][1]);
                }
            }
        }
    }

    // epilogue: y[B,T,C] for the proj GEMM
    const int b_ = bh_ / HH, h = bh_ % HH;
    const float inv0 = 1.f / l0s, inv1 = 1.f / l1s;
#pragma unroll
    for (int n = 0; n < 8; n++) {
        int col = h * 64 + n * 8 + 2 * t;
        int r0 = qrow0 + g;
        *(float2*)&g_y[((size_t)b_ * TT + r0) * CC + col] =
            make_float2(O[n][0] * inv0, O[n][1] * inv0);
        *(float2*)&g_y[((size_t)b_ * TT + r0 + 8) * CC + col] =
            make_float2(O[n][2] * inv1, O[n][3] * inv1);
    }
}

// ---------------------------------------------------------------------------
// Launch
// ---------------------------------------------------------------------------
static const int kAttnSmem = (4 * 64 * 72 + 2 * 256 * 72) * 2;   // 110592 B

extern "C" void kernel_launch(void* const* d_in, const int* in_sizes, int n_in,
                              void* d_out, int out_size) {
    const float* x      = (const float*)d_in[0];
    const float* W_attn = (const float*)d_in[1];
    const float* b_attn = (const float*)d_in[2];
    const float* W_proj = (const float*)d_in[3];
    const float* b_proj = (const float*)d_in[4];
    float* out = (float*)d_out;

    cudaFuncSetAttribute(attn_tc,
                         cudaFuncAttributeMaxDynamicSharedMemorySize, kAttnSmem);

    // 1) qkv projection (scatter into per-head q/k/v)
    gemm_tc<true><<<dim3(NQKV / 128, MM / 128), 512>>>(
        x, W_attn, b_attn, nullptr, CC, NQKV);

    // 2) flash attention
    attn_tc<<<dim3(TT / 256, BB * HH), 512, kAttnSmem>>>();

    // 3) output projection
    gemm_tc<false><<<dim3(CC / 128, MM / 128), 512>>>(
        nullptr, W_proj, b_proj, out, CC, CC);
}

// round 10
// speedup vs baseline: 2.8180x; 1.0178x over previous
#include <cuda_runtime.h>
#include <cuda_bf16.h>
#include <math.h>

// Problem constants
#define BB 2
#define TT 2048
#define CC 1024
#define HH 16
#define HD 64
#define MM (BB*TT)        // 4096
#define NQKV (3*CC)       // 3072

// Scratch (device globals — allocation-free)
__device__ float g_q[(size_t)BB*HH*TT*HD];
__device__ float g_k[(size_t)BB*HH*TT*HD];
__device__ float g_v[(size_t)BB*HH*TT*HD];
// bf16 hi/lo planes for GEMM inputs
__device__ __nv_bfloat16 g_xh[(size_t)MM*CC],   g_xl[(size_t)MM*CC];
__device__ __nv_bfloat16 g_wah[(size_t)NQKV*CC], g_wal[(size_t)NQKV*CC];
__device__ __nv_bfloat16 g_wph[(size_t)CC*CC],  g_wpl[(size_t)CC*CC];
__device__ __nv_bfloat16 g_yh[(size_t)MM*CC],   g_yl[(size_t)MM*CC];

// ---------------------------------------------------------------------------
// Helpers
// ---------------------------------------------------------------------------
__device__ __forceinline__ unsigned bfhi2(float x, float y) {
    __nv_bfloat162 p = __floats2bfloat162_rn(x, y);
    return *(unsigned*)&p;
}
__device__ __forceinline__ unsigned bflo2(float x, float y) {
    float hx = __bfloat162float(__float2bfloat16_rn(x));
    float hy = __bfloat162float(__float2bfloat16_rn(y));
    return bfhi2(x - hx, y - hy);
}
__device__ __forceinline__ void split4bf(float4 v, uint2& h, uint2& l) {
    h.x = bfhi2(v.x, v.y); h.y = bfhi2(v.z, v.w);
    l.x = bflo2(v.x, v.y); l.y = bflo2(v.z, v.w);
}
__device__ __forceinline__ unsigned smem_u32(const void* p) {
    return (unsigned)__cvta_generic_to_shared(p);
}
__device__ __forceinline__ void mma_bf16(float d[4], const unsigned a[4],
                                         unsigned b0, unsigned b1) {
    asm volatile(
        "mma.sync.aligned.m16n8k16.row.col.f32.bf16.bf16.f32 "
        "{%0,%1,%2,%3}, {%4,%5,%6,%7}, {%8,%9}, {%0,%1,%2,%3};"
        : "+f"(d[0]), "+f"(d[1]), "+f"(d[2]), "+f"(d[3])
        : "r"(a[0]), "r"(a[1]), "r"(a[2]), "r"(a[3]), "r"(b0), "r"(b1));
}
__device__ __forceinline__ void ldmx4(unsigned r[4], const void* p) {
    unsigned addr = smem_u32(p);
    asm volatile("ldmatrix.sync.aligned.m8n8.x4.shared.b16 {%0,%1,%2,%3}, [%4];"
                 : "=r"(r[0]), "=r"(r[1]), "=r"(r[2]), "=r"(r[3]) : "r"(addr));
}
__device__ __forceinline__ void ldmx2t(unsigned& r0, unsigned& r1, const void* p) {
    unsigned addr = smem_u32(p);
    asm volatile("ldmatrix.sync.aligned.m8n8.x2.trans.shared.b16 {%0,%1}, [%2];"
                 : "=r"(r0), "=r"(r1) : "r"(addr));
}
__device__ __forceinline__ void cp_async16(unsigned dst, const void* src) {
    asm volatile("cp.async.cg.shared.global [%0], [%1], 16;"
                 :: "r"(dst), "l"(src) : "memory");
}
__device__ __forceinline__ void cp_commit() {
    asm volatile("cp.async.commit_group;" ::: "memory");
}

// ---------------------------------------------------------------------------
// Convert: fp32 -> bf16 hi/lo planes (grid-stride over float4)
// ---------------------------------------------------------------------------
__global__ void cvt_hilo(const float4* __restrict__ src, uint2* __restrict__ dh,
                         uint2* __restrict__ dl, int n4) {
    int i = blockIdx.x * blockDim.x + threadIdx.x;
    if (i < n4) {
        uint2 h, l;
        split4bf(src[i], h, l);
        dh[i] = h;
        dl[i] = l;
    }
}

// ---------------------------------------------------------------------------
// Pipelined bf16x3 GEMM: out[m,n] = sum_k A[m,k]*W[n,k] + bias[n]
// Inputs pre-split bf16 hi/lo in gmem. 128x128 tile, BK=64, 3-stage cp.async,
// one __syncthreads per iteration. 512 threads = 16 warps (4x4), 32x32/warp.
// ---------------------------------------------------------------------------
template<bool QKV_SCATTER>
__global__ __launch_bounds__(512, 1)
void gemm_cp(const __nv_bfloat16* __restrict__ Agh, const __nv_bfloat16* __restrict__ Agl,
             const __nv_bfloat16* __restrict__ Wgh, const __nv_bfloat16* __restrict__ Wgl,
             const float* __restrict__ bias, float* __restrict__ Cout,
             int K, int N) {
    constexpr int BK = 64, LD = 72;
    constexpr int PLANE = 128 * LD;           // bf16 units
    constexpr int STAGE = 4 * PLANE;          // Ah, Al, Wh, Wl
    extern __shared__ __nv_bfloat16 sm[];     // 3 * STAGE

    const int tid = threadIdx.x;
    const int lane = tid & 31, w = tid >> 5;
    const int g = lane >> 2, t = lane & 3;
    const int m0 = blockIdx.y * 128, n0 = blockIdx.x * 128;
    const int wm = (w >> 2) * 32, wn = (w & 3) * 32;

    const int arow = lane & 15, acol8 = (lane >> 4) << 3;
    const int brow = (lane & 7) + ((lane >> 4) << 3), bcol8 = lane & 8;

    // loader: per plane, chunks c = tid and tid+512; row=c>>3, 16B col=(c&7)*8
    const __nv_bfloat16* gsrc[4] = {Agh, Agl, Wgh, Wgl};
    const int rbase[4] = {m0, m0, n0, n0};

#define ISSUE_STAGE(sidx, kt)                                                  \
    do {                                                                       \
        __nv_bfloat16* sb = sm + (sidx) * STAGE;                               \
        _Pragma("unroll")                                                      \
        for (int p = 0; p < 4; p++) {                                          \
            _Pragma("unroll")                                                  \
            for (int rep = 0; rep < 2; rep++) {                                \
                int c = tid + rep * 512;                                       \
                int row = c >> 3, c8 = c & 7;                                  \
                unsigned dst = smem_u32(sb + p * PLANE + row * LD + c8 * 8);   \
                const __nv_bfloat16* gp =                                      \
                    gsrc[p] + (size_t)(rbase[p] + row) * K + (kt) + c8 * 8;    \
                cp_async16(dst, gp);                                           \
            }                                                                  \
        }                                                                      \
        cp_commit();                                                           \
    } while (0)

    float acc[2][4][4] = {};

    const int niter = K / BK;                 // 16
    ISSUE_STAGE(0, 0);
    ISSUE_STAGE(1, BK);

    for (int it = 0; it < niter; it++) {
        if (it + 1 < niter)
            asm volatile("cp.async.wait_group 1;" ::: "memory");
        else
            asm volatile("cp.async.wait_group 0;" ::: "memory");
        __syncthreads();
        if (it + 2 < niter) ISSUE_STAGE((it + 2) % 3, (it + 2) * BK);

        const __nv_bfloat16* Ah = sm + (it % 3) * STAGE;
        const __nv_bfloat16* Al = Ah + PLANE;
        const __nv_bfloat16* Wh = Al + PLANE;
        const __nv_bfloat16* Wl = Wh + PLANE;

#pragma unroll
        for (int s = 0; s < 4; s++) {         // four k16 slices
            const int kc0 = s * 16;
            unsigned ah[2][4], al[2][4];
            ldmx4(ah[0], &Ah[(wm + arow) * LD + kc0 + acol8]);
            ldmx4(ah[1], &Ah[(wm + 16 + arow) * LD + kc0 + acol8]);
            ldmx4(al[0], &Al[(wm + arow) * LD + kc0 + acol8]);
            ldmx4(al[1], &Al[(wm + 16 + arow) * LD + kc0 + acol8]);
            unsigned bh[4][2], bl[4][2];
            {
                unsigned t0[4], t1[4];
                ldmx4(t0, &Wh[(wn + brow) * LD + kc0 + bcol8]);
                ldmx4(t1, &Wh[(wn + 16 + brow) * LD + kc0 + bcol8]);
                bh[0][0] = t0[0]; bh[0][1] = t0[1]; bh[1][0] = t0[2]; bh[1][1] = t0[3];
                bh[2][0] = t1[0]; bh[2][1] = t1[1]; bh[3][0] = t1[2]; bh[3][1] = t1[3];
                ldmx4(t0, &Wl[(wn + brow) * LD + kc0 + bcol8]);
                ldmx4(t1, &Wl[(wn + 16 + brow) * LD + kc0 + bcol8]);
                bl[0][0] = t0[0]; bl[0][1] = t0[1]; bl[1][0] = t0[2]; bl[1][1] = t0[3];
                bl[2][0] = t1[0]; bl[2][1] = t1[1]; bl[3][0] = t1[2]; bl[3][1] = t1[3];
            }
#pragma unroll
            for (int mi = 0; mi < 2; mi++)
#pragma unroll
                for (int ni = 0; ni < 4; ni++)
                    mma_bf16(acc[mi][ni], ah[mi], bh[ni][0], bh[ni][1]);
#pragma unroll
            for (int mi = 0; mi < 2; mi++)
#pragma unroll
                for (int ni = 0; ni < 4; ni++)
                    mma_bf16(acc[mi][ni], al[mi], bh[ni][0], bh[ni][1]);
#pragma unroll
            for (int mi = 0; mi < 2; mi++)
#pragma unroll
                for (int ni = 0; ni < 4; ni++)
                    mma_bf16(acc[mi][ni], ah[mi], bl[ni][0], bl[ni][1]);
        }
    }
#undef ISSUE_STAGE

    // epilogue
#pragma unroll
    for (int mi = 0; mi < 2; mi++)
#pragma unroll
        for (int ni = 0; ni < 4; ni++)
#pragma unroll
            for (int e = 0; e < 4; e++) {
                int row = m0 + wm + mi * 16 + g + ((e >= 2) ? 8 : 0);
                int col = n0 + wn + ni * 8 + 2 * t + (e & 1);
                float v = acc[mi][ni][e] + __ldg(&bias[col]);
                if (QKV_SCATTER) {
                    int which = col >> 10;          // 0=q,1=k,2=v
                    int c = col & (CC - 1);
                    int h = c >> 6, d = c & 63;
                    int b_ = row >> 11;
                    int tt = row & (TT - 1);
                    size_t dst = (((size_t)(b_ * HH + h) * TT + tt) * HD) + d;
                    float* base = (which == 0) ? g_q : ((which == 1) ? g_k : g_v);
                    base[dst] = v;
                } else {
                    Cout[(size_t)row * N + col] = v;
                }
            }
}

// ---------------------------------------------------------------------------
// Tensor-core flash attention (bf16 x3), ldmatrix frags, product-major MMAs.
// Unchanged compute; epilogue now writes y as bf16 hi/lo planes for proj GEMM.
// ---------------------------------------------------------------------------
__global__ __launch_bounds__(512, 1)
void attn_tc() {
    constexpr int LD = 72;
    extern __shared__ __nv_bfloat16 smb[];
    __nv_bfloat16* Khs = smb;                  // [64][72]
    __nv_bfloat16* Kls = Khs + 64 * LD;
    __nv_bfloat16* Vhs = Kls + 64 * LD;        // [64][72]
    __nv_bfloat16* Vls = Vhs + 64 * LD;
    __nv_bfloat16* Phs = Vls + 64 * LD;        // [256][72]
    __nv_bfloat16* Pls = Phs + 256 * LD;

    const int tid = threadIdx.x;
    const int lane = tid & 31, w = tid >> 5;
    const int g = lane >> 2, t = lane & 3;
    const int qi = (int)gridDim.x - 1 - (int)blockIdx.x;  // big tiles first
    const int bh_ = blockIdx.y;

    const float* Qg = g_q + (size_t)bh_ * TT * HD;
    const float* Kg = g_k + (size_t)bh_ * TT * HD;
    const float* Vg = g_v + (size_t)bh_ * TT * HD;

    const int qrow0 = qi * 256 + w * 16;

    const int arow = lane & 15, acol8 = (lane >> 4) << 3;
    const int brow = (lane & 7) + ((lane >> 4) << 3), bcol8 = lane & 8;
    const int rsel = lane & 15;

    unsigned qh[4][4], ql[4][4];
#pragma unroll
    for (int s = 0; s < 4; s++) {
        const int c0 = s * 16 + 2 * t;
        float2 x00 = *(const float2*)&Qg[(size_t)(qrow0 + g) * 64 + c0];
        float2 x01 = *(const float2*)&Qg[(size_t)(qrow0 + g) * 64 + c0 + 8];
        float2 x10 = *(const float2*)&Qg[(size_t)(qrow0 + g + 8) * 64 + c0];
        float2 x11 = *(const float2*)&Qg[(size_t)(qrow0 + g + 8) * 64 + c0 + 8];
        x00.x *= 0.125f; x00.y *= 0.125f; x01.x *= 0.125f; x01.y *= 0.125f;
        x10.x *= 0.125f; x10.y *= 0.125f; x11.x *= 0.125f; x11.y *= 0.125f;
        qh[s][0] = bfhi2(x00.x, x00.y); ql[s][0] = bflo2(x00.x, x00.y);
        qh[s][1] = bfhi2(x10.x, x10.y); ql[s][1] = bflo2(x10.x, x10.y);
        qh[s][2] = bfhi2(x01.x, x01.y); ql[s][2] = bflo2(x01.x, x01.y);
        qh[s][3] = bfhi2(x11.x, x11.y); ql[s][3] = bflo2(x11.x, x11.y);
    }

    float m0s = -1e30f, m1s = -1e30f, l0s = 0.f, l1s = 0.f;
    float O[8][4] = {};

    const int nkb = 4 * qi + 4;
    for (int kb = 0; kb < nkb; kb++) {
        const int k0 = kb * 64;
        __syncthreads();
#pragma unroll
        for (int i = 0; i < 2; i++) {
            int c = tid + 512 * i;
            int key = c >> 4, hd4 = (c & 15) * 4;
            uint2 h, l;
            split4bf(*(const float4*)&Kg[(size_t)(k0 + key) * 64 + hd4], h, l);
            *(uint2*)&Khs[key * LD + hd4] = h;
            *(uint2*)&Kls[key * LD + hd4] = l;
            split4bf(*(const float4*)&Vg[(size_t)(k0 + key) * 64 + hd4], h, l);
            *(uint2*)&Vhs[key * LD + hd4] = h;
            *(uint2*)&Vls[key * LD + hd4] = l;
        }
        __syncthreads();

        if (k0 <= qrow0 + 15) {
            float S[8][4] = {};
#pragma unroll
            for (int s = 0; s < 4; s++) {
                const int kc0 = s * 16;
#pragma unroll
                for (int nh = 0; nh < 2; nh++) {
                    unsigned bh4[2][4], bl4[2][4];
                    const int kr = nh * 32 + brow;
                    ldmx4(bh4[0], &Khs[kr * LD + kc0 + bcol8]);
                    ldmx4(bh4[1], &Khs[(kr + 16) * LD + kc0 + bcol8]);
                    ldmx4(bl4[0], &Kls[kr * LD + kc0 + bcol8]);
                    ldmx4(bl4[1], &Kls[(kr + 16) * LD + kc0 + bcol8]);
#pragma unroll
                    for (int j = 0; j < 4; j++)
                        mma_bf16(S[nh * 4 + j], qh[s],
                                 bh4[j >> 1][(j & 1) * 2], bh4[j >> 1][(j & 1) * 2 + 1]);
#pragma unroll
                    for (int j = 0; j < 4; j++)
                        mma_bf16(S[nh * 4 + j], ql[s],
                                 bh4[j >> 1][(j & 1) * 2], bh4[j >> 1][(j & 1) * 2 + 1]);
#pragma unroll
                    for (int j = 0; j < 4; j++)
                        mma_bf16(S[nh * 4 + j], qh[s],
                                 bl4[j >> 1][(j & 1) * 2], bl4[j >> 1][(j & 1) * 2 + 1]);
                }
            }
            if (k0 + 63 > qrow0) {
                int r0 = qrow0 + g, r1 = r0 + 8;
#pragma unroll
                for (int n = 0; n < 8; n++) {
                    int cb = k0 + n * 8 + 2 * t;
                    if (cb > r0)     S[n][0] = -1e30f;
                    if (cb + 1 > r0) S[n][1] = -1e30f;
                    if (cb > r1)     S[n][2] = -1e30f;
                    if (cb + 1 > r1) S[n][3] = -1e30f;
                }
            }
            float mx0 = -1e30f, mx1 = -1e30f;
#pragma unroll
            for (int n = 0; n < 8; n++) {
                mx0 = fmaxf(mx0, fmaxf(S[n][0], S[n][1]));
                mx1 = fmaxf(mx1, fmaxf(S[n][2], S[n][3]));
            }
            mx0 = fmaxf(mx0, __shfl_xor_sync(0xffffffffu, mx0, 1));
            mx0 = fmaxf(mx0, __shfl_xor_sync(0xffffffffu, mx0, 2));
            mx1 = fmaxf(mx1, __shfl_xor_sync(0xffffffffu, mx1, 1));
            mx1 = fmaxf(mx1, __shfl_xor_sync(0xffffffffu, mx1, 2));
            float mn0 = fmaxf(m0s, mx0), mn1 = fmaxf(m1s, mx1);
            float cr0 = __expf(m0s - mn0), cr1 = __expf(m1s - mn1);
            m0s = mn0; m1s = mn1;
            float rs0 = 0.f, rs1 = 0.f;
#pragma unroll
            for (int n = 0; n < 8; n++) {
                S[n][0] = __expf(S[n][0] - mn0);
                S[n][1] = __expf(S[n][1] - mn0);
                S[n][2] = __expf(S[n][2] - mn1);
                S[n][3] = __expf(S[n][3] - mn1);
                rs0 += S[n][0] + S[n][1];
                rs1 += S[n][2] + S[n][3];
            }
            rs0 += __shfl_xor_sync(0xffffffffu, rs0, 1);
            rs0 += __shfl_xor_sync(0xffffffffu, rs0, 2);
            rs1 += __shfl_xor_sync(0xffffffffu, rs1, 1);
            rs1 += __shfl_xor_sync(0xffffffffu, rs1, 2);
            l0s = l0s * cr0 + rs0;
            l1s = l1s * cr1 + rs1;
#pragma unroll
            for (int n = 0; n < 8; n++) {
                O[n][0] *= cr0; O[n][1] *= cr0;
                O[n][2] *= cr1; O[n][3] *= cr1;
            }
            const int pr0 = (w * 16 + g) * LD, pr1 = pr0 + 8 * LD;
#pragma unroll
            for (int n = 0; n < 8; n++) {
                const int pc = n * 8 + 2 * t;
                *(unsigned*)&Phs[pr0 + pc] = bfhi2(S[n][0], S[n][1]);
                *(unsigned*)&Pls[pr0 + pc] = bflo2(S[n][0], S[n][1]);
                *(unsigned*)&Phs[pr1 + pc] = bfhi2(S[n][2], S[n][3]);
                *(unsigned*)&Pls[pr1 + pc] = bflo2(S[n][2], S[n][3]);
            }
            __syncwarp();
#pragma unroll
            for (int s = 0; s < 4; s++) {
                unsigned pah[4], pal[4];
                ldmx4(pah, &Phs[(w * 16 + arow) * LD + s * 16 + acol8]);
                ldmx4(pal, &Pls[(w * 16 + arow) * LD + s * 16 + acol8]);
                const __nv_bfloat16* vrow_h = &Vhs[(s * 16 + rsel) * LD];
                const __nv_bfloat16* vrow_l = &Vls[(s * 16 + rsel) * LD];
#pragma unroll
                for (int nh = 0; nh < 2; nh++) {
                    unsigned vh[4][2], vl[4][2];
#pragma unroll
                    for (int j = 0; j < 4; j++) {
                        ldmx2t(vh[j][0], vh[j][1], vrow_h + (nh * 4 + j) * 8);
                        ldmx2t(vl[j][0], vl[j][1], vrow_l + (nh * 4 + j) * 8);
                    }
#pragma unroll
                    for (int j = 0; j < 4; j++)
                        mma_bf16(O[nh * 4 + j], pah, vh[j][0], vh[j][1]);
#pragma unroll
                    for (int j = 0; j < 4; j++)
                        mma_bf16(O[nh * 4 + j], pal, vh[j][0], vh[j][1]);
#pragma unroll
                    for (int j = 0; j < 4; j++)
                        mma_bf16(O[nh * 4 + j], pah, vl[j][0], vl[j][1]);
                }
            }
        }
    }

    // epilogue: write y as bf16 hi/lo planes (pairs are 2 consecutive cols)
    const int b_ = bh_ / HH, h = bh_ % HH;
    const float inv0 = 1.f / l0s, inv1 = 1.f / l1s;
    unsigned* yh = (unsigned*)g_yh;
    unsigned* yl = (unsigned*)g_yl;
#pragma unroll
    for (int n = 0; n < 8; n++) {
        int col = h * 64 + n * 8 + 2 * t;
        int r0 = qrow0 + g;
        size_t i0 = (((size_t)b_ * TT + r0) * CC + col) >> 1;
        size_t i1 = (((size_t)b_ * TT + r0 + 8) * CC + col) >> 1;
        float a0 = O[n][0] * inv0, a1 = O[n][1] * inv0;
        float a2 = O[n][2] * inv1, a3 = O[n][3] * inv1;
        yh[i0] = bfhi2(a0, a1); yl[i0] = bflo2(a0, a1);
        yh[i1] = bfhi2(a2, a3); yl[i1] = bflo2(a2, a3);
    }
}

// ---------------------------------------------------------------------------
// Launch: convert x/W -> qkv GEMM -> attention -> proj GEMM
// ---------------------------------------------------------------------------
static const int kGemmSmem = 3 * 4 * 128 * 72 * 2;               // 221184 B
static const int kAttnSmem = (4 * 64 * 72 + 2 * 256 * 72) * 2;   // 110592 B

extern "C" void kernel_launch(void* const* d_in, const int* in_sizes, int n_in,
                              void* d_out, int out_size) {
    const float* x      = (const float*)d_in[0];
    const float* W_attn = (const float*)d_in[1];
    const float* b_attn = (const float*)d_in[2];
    const float* W_proj = (const float*)d_in[3];
    const float* b_proj = (const float*)d_in[4];
    float* out = (float*)d_out;

    cudaFuncSetAttribute(gemm_cp<true>,
                         cudaFuncAttributeMaxDynamicSharedMemorySize, kGemmSmem);
    cudaFuncSetAttribute(gemm_cp<false>,
                         cudaFuncAttributeMaxDynamicSharedMemorySize, kGemmSmem);
    cudaFuncSetAttribute(attn_tc,
                         cudaFuncAttributeMaxDynamicSharedMemorySize, kAttnSmem);

    __nv_bfloat16 *xh, *xl, *wah, *wal, *wph, *wpl, *yh, *yl;
    cudaGetSymbolAddress((void**)&xh, g_xh);   cudaGetSymbolAddress((void**)&xl, g_xl);
    cudaGetSymbolAddress((void**)&wah, g_wah); cudaGetSymbolAddress((void**)&wal, g_wal);
    cudaGetSymbolAddress((void**)&wph, g_wph); cudaGetSymbolAddress((void**)&wpl, g_wpl);
    cudaGetSymbolAddress((void**)&yh, g_yh);   cudaGetSymbolAddress((void**)&yl, g_yl);

    // 0) convert inputs to bf16 hi/lo planes
    cvt_hilo<<<(MM * CC / 4) / 256, 256>>>(
        (const float4*)x, (uint2*)xh, (uint2*)xl, MM * CC / 4);
    cvt_hilo<<<(NQKV * CC / 4) / 256, 256>>>(
        (const float4*)W_attn, (uint2*)wah, (uint2*)wal, NQKV * CC / 4);
    cvt_hilo<<<(CC * CC / 4) / 256, 256>>>(
        (const float4*)W_proj, (uint2*)wph, (uint2*)wpl, CC * CC / 4);

    // 1) qkv projection (scatter into per-head q/k/v)
    gemm_cp<true><<<dim3(NQKV / 128, MM / 128), 512, kGemmSmem>>>(
        xh, xl, wah, wal, b_attn, nullptr, CC, NQKV);

    // 2) flash attention (writes y as bf16 hi/lo)
    attn_tc<<<dim3(TT / 256, BB * HH), 512, kAttnSmem>>>();

    // 3) output projection
    gemm_cp<false><<<dim3(CC / 128, MM / 128), 512, kGemmSmem>>>(
        yh, yl, wph, wpl, b_proj, out, CC, CC);
}

// round 12
// speedup vs baseline: 3.2798x; 1.1639x over previous
#include <cuda_runtime.h>
#include <cuda_bf16.h>
#include <math.h>

// Problem constants
#define BB 2
#define TT 2048
#define CC 1024
#define HH 16
#define HD 64
#define MM (BB*TT)        // 4096
#define NQKV (3*CC)       // 3072

// Scratch (device globals — allocation-free)
__device__ float g_q[(size_t)BB*HH*TT*HD];
__device__ float g_k[(size_t)BB*HH*TT*HD];
__device__ float g_v[(size_t)BB*HH*TT*HD];
// bf16 hi/lo planes for GEMM inputs
__device__ __nv_bfloat16 g_xh[(size_t)MM*CC],   g_xl[(size_t)MM*CC];
__device__ __nv_bfloat16 g_wah[(size_t)NQKV*CC], g_wal[(size_t)NQKV*CC];
__device__ __nv_bfloat16 g_wph[(size_t)CC*CC],  g_wpl[(size_t)CC*CC];
__device__ __nv_bfloat16 g_yh[(size_t)MM*CC],   g_yl[(size_t)MM*CC];

// ---------------------------------------------------------------------------
// Helpers
// ---------------------------------------------------------------------------
__device__ __forceinline__ unsigned bfhi2(float x, float y) {
    __nv_bfloat162 p = __floats2bfloat162_rn(x, y);
    return *(unsigned*)&p;
}
__device__ __forceinline__ unsigned bflo2(float x, float y) {
    float hx = __bfloat162float(__float2bfloat16_rn(x));
    float hy = __bfloat162float(__float2bfloat16_rn(y));
    return bfhi2(x - hx, y - hy);
}
__device__ __forceinline__ void split4bf(float4 v, uint2& h, uint2& l) {
    h.x = bfhi2(v.x, v.y); h.y = bfhi2(v.z, v.w);
    l.x = bflo2(v.x, v.y); l.y = bflo2(v.z, v.w);
}
__device__ __forceinline__ unsigned smem_u32(const void* p) {
    return (unsigned)__cvta_generic_to_shared(p);
}
__device__ __forceinline__ void mma_bf16(float d[4], const unsigned a[4],
                                         unsigned b0, unsigned b1) {
    asm volatile(
        "mma.sync.aligned.m16n8k16.row.col.f32.bf16.bf16.f32 "
        "{%0,%1,%2,%3}, {%4,%5,%6,%7}, {%8,%9}, {%0,%1,%2,%3};"
        : "+f"(d[0]), "+f"(d[1]), "+f"(d[2]), "+f"(d[3])
        : "r"(a[0]), "r"(a[1]), "r"(a[2]), "r"(a[3]), "r"(b0), "r"(b1));
}
__device__ __forceinline__ void ldmx4(unsigned r[4], const void* p) {
    unsigned addr = smem_u32(p);
    asm volatile("ldmatrix.sync.aligned.m8n8.x4.shared.b16 {%0,%1,%2,%3}, [%4];"
                 : "=r"(r[0]), "=r"(r[1]), "=r"(r[2]), "=r"(r[3]) : "r"(addr));
}
__device__ __forceinline__ void ldmx2t(unsigned& r0, unsigned& r1, const void* p) {
    unsigned addr = smem_u32(p);
    asm volatile("ldmatrix.sync.aligned.m8n8.x2.trans.shared.b16 {%0,%1}, [%2];"
                 : "=r"(r0), "=r"(r1) : "r"(addr));
}
__device__ __forceinline__ void cp_async16(unsigned dst, const void* src) {
    asm volatile("cp.async.cg.shared.global [%0], [%1], 16;"
                 :: "r"(dst), "l"(src) : "memory");
}
__device__ __forceinline__ void cp_commit() {
    asm volatile("cp.async.commit_group;" ::: "memory");
}

// ---------------------------------------------------------------------------
// Convert: fp32 -> bf16 hi/lo planes
// ---------------------------------------------------------------------------
__global__ void cvt_hilo(const float4* __restrict__ src, uint2* __restrict__ dh,
                         uint2* __restrict__ dl, int n4) {
    int i = blockIdx.x * blockDim.x + threadIdx.x;
    if (i < n4) {
        uint2 h, l;
        split4bf(src[i], h, l);
        dh[i] = h;
        dl[i] = l;
    }
}

// ---------------------------------------------------------------------------
// Pipelined bf16x3 GEMM: out[m,n] = sum_k A[m,k]*W[n,k] + bias[n]
// 64x128 tile, BK=64, 2-stage cp.async, 256 threads = 8 warps (2x4),
// 32x32 per warp. smem 110592B/CTA -> 2 CTAs/SM.
// ---------------------------------------------------------------------------
template<bool QKV_SCATTER>
__global__ __launch_bounds__(256, 2)
void gemm_cp(const __nv_bfloat16* __restrict__ Agh, const __nv_bfloat16* __restrict__ Agl,
             const __nv_bfloat16* __restrict__ Wgh, const __nv_bfloat16* __restrict__ Wgl,
             const float* __restrict__ bias, float* __restrict__ Cout,
             int K, int N) {
    constexpr int BK = 64, LD = 72;
    constexpr int APLANE = 64 * LD;           // bf16 units
    constexpr int WPLANE = 128 * LD;
    constexpr int STAGE = 2 * APLANE + 2 * WPLANE;   // Ah, Al, Wh, Wl
    extern __shared__ __nv_bfloat16 sm[];     // 2 * STAGE

    const int tid = threadIdx.x;
    const int lane = tid & 31, w = tid >> 5;
    const int g = lane >> 2, t = lane & 3;
    const int m0 = blockIdx.y * 64, n0 = blockIdx.x * 128;
    const int wm = (w >> 2) * 32, wn = (w & 3) * 32;

    const int arow = lane & 15, acol8 = (lane >> 4) << 3;
    const int brow = (lane & 7) + ((lane >> 4) << 3), bcol8 = lane & 8;

#define ISSUE_STAGE(sidx, kt)                                                  \
    do {                                                                       \
        __nv_bfloat16* sb = sm + (sidx) * STAGE;                               \
        _Pragma("unroll")                                                      \
        for (int rep = 0; rep < 2; rep++) {  /* A planes: 512 chunks each */   \
            int c = tid + rep * 256;                                           \
            int row = c >> 3, c8 = c & 7;                                      \
            cp_async16(smem_u32(sb + row * LD + c8 * 8),                       \
                       Agh + (size_t)(m0 + row) * K + (kt) + c8 * 8);          \
            cp_async16(smem_u32(sb + APLANE + row * LD + c8 * 8),              \
                       Agl + (size_t)(m0 + row) * K + (kt) + c8 * 8);          \
        }                                                                      \
        _Pragma("unroll")                                                      \
        for (int rep = 0; rep < 4; rep++) {  /* W planes: 1024 chunks each */  \
            int c = tid + rep * 256;                                           \
            int row = c >> 3, c8 = c & 7;                                      \
            cp_async16(smem_u32(sb + 2 * APLANE + row * LD + c8 * 8),          \
                       Wgh + (size_t)(n0 + row) * K + (kt) + c8 * 8);          \
            cp_async16(smem_u32(sb + 2 * APLANE + WPLANE + row * LD + c8 * 8), \
                       Wgl + (size_t)(n0 + row) * K + (kt) + c8 * 8);          \
        }                                                                      \
        cp_commit();                                                           \
    } while (0)

    float acc[2][4][4] = {};

    const int niter = K / BK;                 // 16
    ISSUE_STAGE(0, 0);
    ISSUE_STAGE(1, BK);

    for (int it = 0; it < niter; it++) {
        if (it + 1 < niter)
            asm volatile("cp.async.wait_group 1;" ::: "memory");
        else
            asm volatile("cp.async.wait_group 0;" ::: "memory");
        __syncthreads();

        const __nv_bfloat16* Ah = sm + (it & 1) * STAGE;
        const __nv_bfloat16* Al = Ah + APLANE;
        const __nv_bfloat16* Wh = Al + APLANE;
        const __nv_bfloat16* Wl = Wh + WPLANE;

#pragma unroll
        for (int s = 0; s < 4; s++) {         // four k16 slices
            const int kc0 = s * 16;
            unsigned ah[2][4], al[2][4];
            ldmx4(ah[0], &Ah[(wm + arow) * LD + kc0 + acol8]);
            ldmx4(ah[1], &Ah[(wm + 16 + arow) * LD + kc0 + acol8]);
            ldmx4(al[0], &Al[(wm + arow) * LD + kc0 + acol8]);
            ldmx4(al[1], &Al[(wm + 16 + arow) * LD + kc0 + acol8]);
            unsigned bh[4][2], bl[4][2];
            {
                unsigned t0[4], t1[4];
                ldmx4(t0, &Wh[(wn + brow) * LD + kc0 + bcol8]);
                ldmx4(t1, &Wh[(wn + 16 + brow) * LD + kc0 + bcol8]);
                bh[0][0] = t0[0]; bh[0][1] = t0[1]; bh[1][0] = t0[2]; bh[1][1] = t0[3];
                bh[2][0] = t1[0]; bh[2][1] = t1[1]; bh[3][0] = t1[2]; bh[3][1] = t1[3];
                ldmx4(t0, &Wl[(wn + brow) * LD + kc0 + bcol8]);
                ldmx4(t1, &Wl[(wn + 16 + brow) * LD + kc0 + bcol8]);
                bl[0][0] = t0[0]; bl[0][1] = t0[1]; bl[1][0] = t0[2]; bl[1][1] = t0[3];
                bl[2][0] = t1[0]; bl[2][1] = t1[1]; bl[3][0] = t1[2]; bl[3][1] = t1[3];
            }
#pragma unroll
            for (int mi = 0; mi < 2; mi++)
#pragma unroll
                for (int ni = 0; ni < 4; ni++)
                    mma_bf16(acc[mi][ni], ah[mi], bh[ni][0], bh[ni][1]);
#pragma unroll
            for (int mi = 0; mi < 2; mi++)
#pragma unroll
                for (int ni = 0; ni < 4; ni++)
                    mma_bf16(acc[mi][ni], al[mi], bh[ni][0], bh[ni][1]);
#pragma unroll
            for (int mi = 0; mi < 2; mi++)
#pragma unroll
                for (int ni = 0; ni < 4; ni++)
                    mma_bf16(acc[mi][ni], ah[mi], bl[ni][0], bl[ni][1]);
        }
        __syncthreads();                      // done reading buffer (it&1)
        if (it + 2 < niter) ISSUE_STAGE((it + 2) & 1, (it + 2) * BK);
    }
#undef ISSUE_STAGE

    // epilogue
#pragma unroll
    for (int mi = 0; mi < 2; mi++)
#pragma unroll
        for (int ni = 0; ni < 4; ni++)
#pragma unroll
            for (int e = 0; e < 4; e++) {
                int row = m0 + wm + mi * 16 + g + ((e >= 2) ? 8 : 0);
                int col = n0 + wn + ni * 8 + 2 * t + (e & 1);
                float v = acc[mi][ni][e] + __ldg(&bias[col]);
                if (QKV_SCATTER) {
                    int which = col >> 10;          // 0=q,1=k,2=v
                    int c = col & (CC - 1);
                    int h = c >> 6, d = c & 63;
                    int b_ = row >> 11;
                    int tt = row & (TT - 1);
                    size_t dst = (((size_t)(b_ * HH + h) * TT + tt) * HD) + d;
                    float* base = (which == 0) ? g_q : ((which == 1) ? g_k : g_v);
                    base[dst] = v;
                } else {
                    Cout[(size_t)row * N + col] = v;
                }
            }
}

// ---------------------------------------------------------------------------
// Tensor-core flash attention (bf16 x3), 128-row Q tiles, 256 threads,
// 2 CTAs/SM. Inner compute identical to the passing version.
// ---------------------------------------------------------------------------
__global__ __launch_bounds__(256, 2)
void attn_tc() {
    constexpr int LD = 72;
    extern __shared__ __nv_bfloat16 smb[];
    __nv_bfloat16* Khs = smb;                  // [64][72]
    __nv_bfloat16* Kls = Khs + 64 * LD;
    __nv_bfloat16* Vhs = Kls + 64 * LD;        // [64][72]
    __nv_bfloat16* Vls = Vhs + 64 * LD;
    __nv_bfloat16* Phs = Vls + 64 * LD;        // [128][72]
    __nv_bfloat16* Pls = Phs + 128 * LD;

    const int tid = threadIdx.x;
    const int lane = tid & 31, w = tid >> 5;
    const int g = lane >> 2, t = lane & 3;
    const int qi = (int)gridDim.x - 1 - (int)blockIdx.x;  // big tiles first
    const int bh_ = blockIdx.y;

    const float* Qg = g_q + (size_t)bh_ * TT * HD;
    const float* Kg = g_k + (size_t)bh_ * TT * HD;
    const float* Vg = g_v + (size_t)bh_ * TT * HD;

    const int qrow0 = qi * 128 + w * 16;

    const int arow = lane & 15, acol8 = (lane >> 4) << 3;
    const int brow = (lane & 7) + ((lane >> 4) << 3), bcol8 = lane & 8;
    const int rsel = lane & 15;

    unsigned qh[4][4], ql[4][4];
#pragma unroll
    for (int s = 0; s < 4; s++) {
        const int c0 = s * 16 + 2 * t;
        float2 x00 = *(const float2*)&Qg[(size_t)(qrow0 + g) * 64 + c0];
        float2 x01 = *(const float2*)&Qg[(size_t)(qrow0 + g) * 64 + c0 + 8];
        float2 x10 = *(const float2*)&Qg[(size_t)(qrow0 + g + 8) * 64 + c0];
        float2 x11 = *(const float2*)&Qg[(size_t)(qrow0 + g + 8) * 64 + c0 + 8];
        x00.x *= 0.125f; x00.y *= 0.125f; x01.x *= 0.125f; x01.y *= 0.125f;
        x10.x *= 0.125f; x10.y *= 0.125f; x11.x *= 0.125f; x11.y *= 0.125f;
        qh[s][0] = bfhi2(x00.x, x00.y); ql[s][0] = bflo2(x00.x, x00.y);
        qh[s][1] = bfhi2(x10.x, x10.y); ql[s][1] = bflo2(x10.x, x10.y);
        qh[s][2] = bfhi2(x01.x, x01.y); ql[s][2] = bflo2(x01.x, x01.y);
        qh[s][3] = bfhi2(x11.x, x11.y); ql[s][3] = bflo2(x11.x, x11.y);
    }

    float m0s = -1e30f, m1s = -1e30f, l0s = 0.f, l1s = 0.f;
    float O[8][4] = {};

    const int nkb = 2 * qi + 2;
    for (int kb = 0; kb < nkb; kb++) {
        const int k0 = kb * 64;
        __syncthreads();
#pragma unroll
        for (int i = 0; i < 4; i++) {
            int c = tid + 256 * i;
            int key = c >> 4, hd4 = (c & 15) * 4;
            uint2 h, l;
            split4bf(*(const float4*)&Kg[(size_t)(k0 + key) * 64 + hd4], h, l);
            *(uint2*)&Khs[key * LD + hd4] = h;
            *(uint2*)&Kls[key * LD + hd4] = l;
            split4bf(*(const float4*)&Vg[(size_t)(k0 + key) * 64 + hd4], h, l);
            *(uint2*)&Vhs[key * LD + hd4] = h;
            *(uint2*)&Vls[key * LD + hd4] = l;
        }
        __syncthreads();

        if (k0 <= qrow0 + 15) {
            float S[8][4] = {};
#pragma unroll
            for (int s = 0; s < 4; s++) {
                const int kc0 = s * 16;
#pragma unroll
                for (int nh = 0; nh < 2; nh++) {
                    unsigned bh4[2][4], bl4[2][4];
                    const int kr = nh * 32 + brow;
                    ldmx4(bh4[0], &Khs[kr * LD + kc0 + bcol8]);
                    ldmx4(bh4[1], &Khs[(kr + 16) * LD + kc0 + bcol8]);
                    ldmx4(bl4[0], &Kls[kr * LD + kc0 + bcol8]);
                    ldmx4(bl4[1], &Kls[(kr + 16) * LD + kc0 + bcol8]);
#pragma unroll
                    for (int j = 0; j < 4; j++)
                        mma_bf16(S[nh * 4 + j], qh[s],
                                 bh4[j >> 1][(j & 1) * 2], bh4[j >> 1][(j & 1) * 2 + 1]);
#pragma unroll
                    for (int j = 0; j < 4; j++)
                        mma_bf16(S[nh * 4 + j], ql[s],
                                 bh4[j >> 1][(j & 1) * 2], bh4[j >> 1][(j & 1) * 2 + 1]);
#pragma unroll
                    for (int j = 0; j < 4; j++)
                        mma_bf16(S[nh * 4 + j], qh[s],
                                 bl4[j >> 1][(j & 1) * 2], bl4[j >> 1][(j & 1) * 2 + 1]);
                }
            }
            if (k0 + 63 > qrow0) {
                int r0 = qrow0 + g, r1 = r0 + 8;
#pragma unroll
                for (int n = 0; n < 8; n++) {
                    int cb = k0 + n * 8 + 2 * t;
                    if (cb > r0)     S[n][0] = -1e30f;
                    if (cb + 1 > r0) S[n][1] = -1e30f;
                    if (cb > r1)     S[n][2] = -1e30f;
                    if (cb + 1 > r1) S[n][3] = -1e30f;
                }
            }
            float mx0 = -1e30f, mx1 = -1e30f;
#pragma unroll
            for (int n = 0; n < 8; n++) {
                mx0 = fmaxf(mx0, fmaxf(S[n][0], S[n][1]));
                mx1 = fmaxf(mx1, fmaxf(S[n][2], S[n][3]));
            }
            mx0 = fmaxf(mx0, __shfl_xor_sync(0xffffffffu, mx0, 1));
            mx0 = fmaxf(mx0, __shfl_xor_sync(0xffffffffu, mx0, 2));
            mx1 = fmaxf(mx1, __shfl_xor_sync(0xffffffffu, mx1, 1));
            mx1 = fmaxf(mx1, __shfl_xor_sync(0xffffffffu, mx1, 2));
            float mn0 = fmaxf(m0s, mx0), mn1 = fmaxf(m1s, mx1);
            float cr0 = __expf(m0s - mn0), cr1 = __expf(m1s - mn1);
            m0s = mn0; m1s = mn1;
            float rs0 = 0.f, rs1 = 0.f;
#pragma unroll
            for (int n = 0; n < 8; n++) {
                S[n][0] = __expf(S[n][0] - mn0);
                S[n][1] = __expf(S[n][1] - mn0);
                S[n][2] = __expf(S[n][2] - mn1);
                S[n][3] = __expf(S[n][3] - mn1);
                rs0 += S[n][0] + S[n][1];
                rs1 += S[n][2] + S[n][3];
            }
            rs0 += __shfl_xor_sync(0xffffffffu, rs0, 1);
            rs0 += __shfl_xor_sync(0xffffffffu, rs0, 2);
            rs1 += __shfl_xor_sync(0xffffffffu, rs1, 1);
            rs1 += __shfl_xor_sync(0xffffffffu, rs1, 2);
            l0s = l0s * cr0 + rs0;
            l1s = l1s * cr1 + rs1;
#pragma unroll
            for (int n = 0; n < 8; n++) {
                O[n][0] *= cr0; O[n][1] *= cr0;
                O[n][2] *= cr1; O[n][3] *= cr1;
            }
            const int pr0 = (w * 16 + g) * LD, pr1 = pr0 + 8 * LD;
#pragma unroll
            for (int n = 0; n < 8; n++) {
                const int pc = n * 8 + 2 * t;
                *(unsigned*)&Phs[pr0 + pc] = bfhi2(S[n][0], S[n][1]);
                *(unsigned*)&Pls[pr0 + pc] = bflo2(S[n][0], S[n][1]);
                *(unsigned*)&Phs[pr1 + pc] = bfhi2(S[n][2], S[n][3]);
                *(unsigned*)&Pls[pr1 + pc] = bflo2(S[n][2], S[n][3]);
            }
            __syncwarp();
#pragma unroll
            for (int s = 0; s < 4; s++) {
                unsigned pah[4], pal[4];
                ldmx4(pah, &Phs[(w * 16 + arow) * LD + s * 16 + acol8]);
                ldmx4(pal, &Pls[(w * 16 + arow) * LD + s * 16 + acol8]);
                const __nv_bfloat16* vrow_h = &Vhs[(s * 16 + rsel) * LD];
                const __nv_bfloat16* vrow_l = &Vls[(s * 16 + rsel) * LD];
#pragma unroll
                for (int nh = 0; nh < 2; nh++) {
                    unsigned vh[4][2], vl[4][2];
#pragma unroll
                    for (int j = 0; j < 4; j++) {
                        ldmx2t(vh[j][0], vh[j][1], vrow_h + (nh * 4 + j) * 8);
                        ldmx2t(vl[j][0], vl[j][1], vrow_l + (nh * 4 + j) * 8);
                    }
#pragma unroll
                    for (int j = 0; j < 4; j++)
                        mma_bf16(O[nh * 4 + j], pah, vh[j][0], vh[j][1]);
#pragma unroll
                    for (int j = 0; j < 4; j++)
                        mma_bf16(O[nh * 4 + j], pal, vh[j][0], vh[j][1]);
#pragma unroll
                    for (int j = 0; j < 4; j++)
                        mma_bf16(O[nh * 4 + j], pah, vl[j][0], vl[j][1]);
                }
            }
        }
    }

    // epilogue: write y as bf16 hi/lo planes (pairs are 2 consecutive cols)
    const int b_ = bh_ / HH, h = bh_ % HH;
    const float inv0 = 1.f / l0s, inv1 = 1.f / l1s;
    unsigned* yh = (unsigned*)g_yh;
    unsigned* yl = (unsigned*)g_yl;
#pragma unroll
    for (int n = 0; n < 8; n++) {
        int col = h * 64 + n * 8 + 2 * t;
        int r0 = qrow0 + g;
        size_t i0 = (((size_t)b_ * TT + r0) * CC + col) >> 1;
        size_t i1 = (((size_t)b_ * TT + r0 + 8) * CC + col) >> 1;
        float a0 = O[n][0] * inv0, a1 = O[n][1] * inv0;
        float a2 = O[n][2] * inv1, a3 = O[n][3] * inv1;
        yh[i0] = bfhi2(a0, a1); yl[i0] = bflo2(a0, a1);
        yh[i1] = bfhi2(a2, a3); yl[i1] = bflo2(a2, a3);
    }
}

// ---------------------------------------------------------------------------
// Launch: convert x/W -> qkv GEMM -> attention -> proj GEMM
// ---------------------------------------------------------------------------
static const int kGemmSmem = 2 * (2 * 64 * 72 + 2 * 128 * 72) * 2;   // 110592 B
static const int kAttnSmem = (4 * 64 * 72 + 2 * 128 * 72) * 2;       // 73728 B

extern "C" void kernel_launch(void* const* d_in, const int* in_sizes, int n_in,
                              void* d_out, int out_size) {
    const float* x      = (const float*)d_in[0];
    const float* W_attn = (const float*)d_in[1];
    const float* b_attn = (const float*)d_in[2];
    const float* W_proj = (const float*)d_in[3];
    const float* b_proj = (const float*)d_in[4];
    float* out = (float*)d_out;

    cudaFuncSetAttribute(gemm_cp<true>,
                         cudaFuncAttributeMaxDynamicSharedMemorySize, kGemmSmem);
    cudaFuncSetAttribute(gemm_cp<false>,
                         cudaFuncAttributeMaxDynamicSharedMemorySize, kGemmSmem);
    cudaFuncSetAttribute(attn_tc,
                         cudaFuncAttributeMaxDynamicSharedMemorySize, kAttnSmem);

    __nv_bfloat16 *xh, *xl, *wah, *wal, *wph, *wpl, *yh, *yl;
    cudaGetSymbolAddress((void**)&xh, g_xh);   cudaGetSymbolAddress((void**)&xl, g_xl);
    cudaGetSymbolAddress((void**)&wah, g_wah); cudaGetSymbolAddress((void**)&wal, g_wal);
    cudaGetSymbolAddress((void**)&wph, g_wph); cudaGetSymbolAddress((void**)&wpl, g_wpl);
    cudaGetSymbolAddress((void**)&yh, g_yh);   cudaGetSymbolAddress((void**)&yl, g_yl);

    // 0) convert inputs to bf16 hi/lo planes
    cvt_hilo<<<(MM * CC / 4) / 256, 256>>>(
        (const float4*)x, (uint2*)xh, (uint2*)xl, MM * CC / 4);
    cvt_hilo<<<(NQKV * CC / 4) / 256, 256>>>(
        (const float4*)W_attn, (uint2*)wah, (uint2*)wal, NQKV * CC / 4);
    cvt_hilo<<<(CC * CC / 4) / 256, 256>>>(
        (const float4*)W_proj, (uint2*)wph, (uint2*)wpl, CC * CC / 4);

    // 1) qkv projection (scatter into per-head q/k/v)
    gemm_cp<true><<<dim3(NQKV / 128, MM / 64), 256, kGemmSmem>>>(
        xh, xl, wah, wal, b_attn, nullptr, CC, NQKV);

    // 2) flash attention (writes y as bf16 hi/lo)
    attn_tc<<<dim3(TT / 128, BB * HH), 256, kAttnSmem>>>();

    // 3) output projection
    gemm_cp<false><<<dim3(CC / 128, MM / 64), 256, kGemmSmem>>>(
        yh, yl, wph, wpl, b_proj, out, CC, CC);
}